// round 1
// baseline (speedup 1.0000x reference)
#include <cuda_runtime.h>
#include <cstdint>
#include <cstddef>

// ---------------- Problem constants ----------------
#define IMG   224
#define PATCH 16
#define CIN   3
#define EMB   768
#define DEPTH 12
#define NHEAD 12
#define HD    64
#define FF    3072
#define NCLS  1000
#define BATCH 32
#define NP    196            // (224/16)^2
#define NTOK  197            // NP + 1
#define ROWS  (BATCH * NTOK) // 6304
#define PROWS (BATCH * NP)   // 6272
#define EPS   1e-5f

// ---------------- Scratch (device globals; no cudaMalloc allowed) -----------
__device__ float g_h  [ROWS * EMB];
__device__ float g_q  [ROWS * EMB];
__device__ float g_k  [ROWS * EMB];
__device__ float g_v  [ROWS * EMB];
__device__ float g_t  [ROWS * EMB];
__device__ float g_x  [ROWS * EMB];
__device__ float g_ff [ROWS * FF];
__device__ float g_sc [(size_t)BATCH * NHEAD * NTOK * NTOK];
__device__ float g_im [PROWS * EMB];
__device__ float g_wt [EMB * EMB];
__device__ float g_cls[BATCH * EMB];

// ---------------- GEMM: C = A[MxK] @ B[KxN] (+bias, relu) -------------------
#define BM 128
#define BN 128
#define BK 16
#define TM 8
#define TN 8

__global__ __launch_bounds__(256)
void gemm_nn(const float* __restrict__ A, const float* __restrict__ B,
             const float* __restrict__ bias, float* __restrict__ C,
             int M, int N, int K, int do_relu)
{
    __shared__ __align__(16) float As[BK][BM];
    __shared__ __align__(16) float Bs[BK][BN];

    const int tid  = threadIdx.x;
    const int row0 = blockIdx.y * BM;
    const int col0 = blockIdx.x * BN;
    const int tx   = tid & 15;   // 16 col groups of TN
    const int ty   = tid >> 4;   // 16 row groups of TM

    float acc[TM][TN];
    #pragma unroll
    for (int i = 0; i < TM; i++)
        #pragma unroll
        for (int j = 0; j < TN; j++) acc[i][j] = 0.f;

    for (int kt = 0; kt < K; kt += BK) {
        // load A tile (BM x BK), store transposed into As[k][m]
        #pragma unroll
        for (int l = 0; l < 2; l++) {
            int idx = tid + l * 256;        // 0..511 float4 slots
            int ar  = idx >> 2;             // 0..127 row in tile
            int ac  = (idx & 3) << 2;       // 0,4,8,12 col in tile
            int gr  = row0 + ar;
            float4 val = make_float4(0.f, 0.f, 0.f, 0.f);
            if (gr < M)
                val = *reinterpret_cast<const float4*>(&A[(size_t)gr * K + kt + ac]);
            As[ac + 0][ar] = val.x;
            As[ac + 1][ar] = val.y;
            As[ac + 2][ar] = val.z;
            As[ac + 3][ar] = val.w;
        }
        // load B tile (BK x BN)
        #pragma unroll
        for (int l = 0; l < 2; l++) {
            int idx = tid + l * 256;
            int br  = idx >> 5;             // 0..15
            int bc  = (idx & 31) << 2;      // 0..124 step 4
            *reinterpret_cast<float4*>(&Bs[br][bc]) =
                *reinterpret_cast<const float4*>(&B[(size_t)(kt + br) * N + col0 + bc]);
        }
        __syncthreads();

        #pragma unroll
        for (int k = 0; k < BK; k++) {
            float ra[TM], rb[TN];
            #pragma unroll
            for (int i = 0; i < TM; i += 4)
                *reinterpret_cast<float4*>(&ra[i]) =
                    *reinterpret_cast<const float4*>(&As[k][ty * TM + i]);
            #pragma unroll
            for (int j = 0; j < TN; j += 4)
                *reinterpret_cast<float4*>(&rb[j]) =
                    *reinterpret_cast<const float4*>(&Bs[k][tx * TN + j]);
            #pragma unroll
            for (int i = 0; i < TM; i++)
                #pragma unroll
                for (int j = 0; j < TN; j++)
                    acc[i][j] = fmaf(ra[i], rb[j], acc[i][j]);
        }
        __syncthreads();
    }

    const bool hb = (bias != nullptr);
    #pragma unroll
    for (int i = 0; i < TM; i++) {
        int gr = row0 + ty * TM + i;
        if (gr >= M) continue;
        #pragma unroll
        for (int j = 0; j < TN; j++) {
            int gc = col0 + tx * TN + j;
            float v = acc[i][j];
            if (hb) v += bias[gc];
            if (do_relu) v = fmaxf(v, 0.f);
            C[(size_t)gr * N + gc] = v;
        }
    }
}

// ---------------- im2col for the 16x16/s16 conv ----------------------------
__global__ void im2col_kernel(const float* __restrict__ x, float* __restrict__ out)
{
    int idx = blockIdx.x * blockDim.x + threadIdx.x;
    if (idx >= PROWS * EMB) return;
    int row = idx / EMB;       // b*196 + p
    int k   = idx % EMB;       // c*256 + ph*16 + pw
    int b   = row / NP;
    int p   = row % NP;
    int py  = p / 14, px = p % 14;
    int c   = k / 256;
    int r2  = k % 256;
    int ph  = r2 / PATCH, pw = r2 % PATCH;
    out[idx] = x[(((size_t)b * CIN + c) * IMG + (py * PATCH + ph)) * IMG
                 + (px * PATCH + pw)];
}

// transpose conv_w (E x K) -> (K x E)
__global__ void transpose_w(const float* __restrict__ w, float* __restrict__ wt)
{
    int idx = blockIdx.x * blockDim.x + threadIdx.x;
    if (idx >= EMB * EMB) return;
    int k = idx / EMB;
    int e = idx % EMB;
    wt[idx] = w[(size_t)e * EMB + k];
}

// build h0 = concat(cls, patches) + pos_emb
__global__ void embed_kernel(const float* __restrict__ patch,
                             const float* __restrict__ cls_tok,
                             const float* __restrict__ pos,
                             float* __restrict__ h)
{
    int idx = blockIdx.x * blockDim.x + threadIdx.x;
    if (idx >= ROWS * EMB) return;
    int row = idx / EMB;
    int e   = idx % EMB;
    int b   = row / NTOK;
    int n   = row % NTOK;
    float base = (n == 0) ? cls_tok[e]
                          : patch[((size_t)b * NP + (n - 1)) * EMB + e];
    h[idx] = base + pos[n * EMB + e];
}

// ---------------- attention: scores = Q Kᵀ * scale --------------------------
__global__ __launch_bounds__(256)
void attn_scores(const float* __restrict__ q, const float* __restrict__ k,
                 float* __restrict__ scores)
{
    const int bh = blockIdx.z;               // b*NHEAD + h
    const int b  = bh / NHEAD;
    const int hh = bh % NHEAD;
    const int q0 = blockIdx.y * 32;
    const int k0 = blockIdx.x * 32;
    const float scale = 0.036084391824f;     // 1/sqrt(768)

    __shared__ __align__(16) float Qs[32][65];
    __shared__ __align__(16) float Ks[32][65];

    const int tid = threadIdx.x;
    const float* Qb = q + (size_t)b * NTOK * EMB + hh * HD;
    const float* Kb = k + (size_t)b * NTOK * EMB + hh * HD;

    #pragma unroll
    for (int l = 0; l < 2; l++) {
        int idx = tid + l * 256;       // 512 float4 slots (32 rows x 16 f4)
        int r   = idx >> 4;
        int c4  = (idx & 15) << 2;
        float4 vq = make_float4(0.f,0.f,0.f,0.f);
        float4 vk = make_float4(0.f,0.f,0.f,0.f);
        if (q0 + r < NTOK)
            vq = *reinterpret_cast<const float4*>(&Qb[(size_t)(q0 + r) * EMB + c4]);
        if (k0 + r < NTOK)
            vk = *reinterpret_cast<const float4*>(&Kb[(size_t)(k0 + r) * EMB + c4]);
        Qs[r][c4+0]=vq.x; Qs[r][c4+1]=vq.y; Qs[r][c4+2]=vq.z; Qs[r][c4+3]=vq.w;
        Ks[r][c4+0]=vk.x; Ks[r][c4+1]=vk.y; Ks[r][c4+2]=vk.z; Ks[r][c4+3]=vk.w;
    }
    __syncthreads();

    const int tx = tid & 15;   // k cols pairs
    const int ty = tid >> 4;   // q rows pairs
    float acc[2][2] = {{0.f,0.f},{0.f,0.f}};
    #pragma unroll
    for (int kk = 0; kk < HD; kk++) {
        float a0 = Qs[ty*2+0][kk], a1 = Qs[ty*2+1][kk];
        float b0 = Ks[tx*2+0][kk], b1 = Ks[tx*2+1][kk];
        acc[0][0] = fmaf(a0,b0,acc[0][0]);
        acc[0][1] = fmaf(a0,b1,acc[0][1]);
        acc[1][0] = fmaf(a1,b0,acc[1][0]);
        acc[1][1] = fmaf(a1,b1,acc[1][1]);
    }
    #pragma unroll
    for (int i = 0; i < 2; i++) {
        int qr = q0 + ty*2 + i;
        if (qr >= NTOK) continue;
        #pragma unroll
        for (int j = 0; j < 2; j++) {
            int kc = k0 + tx*2 + j;
            if (kc >= NTOK) continue;
            scores[((size_t)bh * NTOK + qr) * NTOK + kc] = acc[i][j] * scale;
        }
    }
}

// ---------------- softmax over last dim (197), one warp per row -------------
__global__ __launch_bounds__(256)
void softmax_kernel(float* __restrict__ scores, int nrows)
{
    int row = blockIdx.x * 8 + (threadIdx.x >> 5);
    if (row >= nrows) return;
    int lane = threadIdx.x & 31;
    float* p = scores + (size_t)row * NTOK;

    float vals[7];
    float mx = -1e30f;
    #pragma unroll
    for (int i = 0; i < 7; i++) {
        int c = i * 32 + lane;
        vals[i] = (c < NTOK) ? p[c] : -1e30f;
        mx = fmaxf(mx, vals[i]);
    }
    #pragma unroll
    for (int o = 16; o; o >>= 1) mx = fmaxf(mx, __shfl_xor_sync(0xffffffffu, mx, o));

    float s = 0.f;
    #pragma unroll
    for (int i = 0; i < 7; i++) {
        vals[i] = expf(vals[i] - mx);
        s += vals[i];
    }
    #pragma unroll
    for (int o = 16; o; o >>= 1) s += __shfl_xor_sync(0xffffffffu, s, o);
    float inv = 1.f / s;
    #pragma unroll
    for (int i = 0; i < 7; i++) {
        int c = i * 32 + lane;
        if (c < NTOK) p[c] = vals[i] * inv;
    }
}

// ---------------- out = attn @ V, written into [b,q,h*64+d] -----------------
__global__ __launch_bounds__(256)
void attn_av(const float* __restrict__ attn, const float* __restrict__ v,
             float* __restrict__ out)
{
    const int bh = blockIdx.y;
    const int b  = bh / NHEAD;
    const int hh = bh % NHEAD;
    const int q0 = blockIdx.x * 32;

    __shared__ __align__(16) float As[32][33];   // attn tile (q, kk)
    __shared__ __align__(16) float Vs[32][64];   // v tile (kk, d)

    const int tid = threadIdx.x;
    const int tx  = tid & 15;   // d: 16 groups of 4
    const int ty  = tid >> 4;   // q: 16 groups of 2
    const float* Arow = attn + (size_t)bh * NTOK * NTOK;
    const float* Vb   = v + (size_t)b * NTOK * EMB + hh * HD;

    float acc[2][4] = {};

    for (int kt = 0; kt < NTOK; kt += 32) {
        // attn tile: 32x32, scalar loads with guards
        {
            int base = tid * 4;
            int r = base >> 5;
            int c = base & 31;
            #pragma unroll
            for (int u = 0; u < 4; u++) {
                int qr = q0 + r, kc = kt + c + u;
                As[r][c + u] = (qr < NTOK && kc < NTOK)
                               ? Arow[(size_t)qr * NTOK + kc] : 0.f;
            }
        }
        // V tile: 32 rows x 64 d
        #pragma unroll
        for (int l = 0; l < 2; l++) {
            int idx = tid + l * 256;
            int r   = idx >> 4;
            int c4  = (idx & 15) << 2;
            float4 val = make_float4(0.f,0.f,0.f,0.f);
            if (kt + r < NTOK)
                val = *reinterpret_cast<const float4*>(&Vb[(size_t)(kt + r) * EMB + c4]);
            *reinterpret_cast<float4*>(&Vs[r][c4]) = val;
        }
        __syncthreads();

        #pragma unroll
        for (int kk = 0; kk < 32; kk++) {
            float a0 = As[ty*2+0][kk];
            float a1 = As[ty*2+1][kk];
            float rb[4];
            *reinterpret_cast<float4*>(rb) =
                *reinterpret_cast<const float4*>(&Vs[kk][tx*4]);
            #pragma unroll
            for (int j = 0; j < 4; j++) {
                acc[0][j] = fmaf(a0, rb[j], acc[0][j]);
                acc[1][j] = fmaf(a1, rb[j], acc[1][j]);
            }
        }
        __syncthreads();
    }

    #pragma unroll
    for (int i = 0; i < 2; i++) {
        int qr = q0 + ty*2 + i;
        if (qr >= NTOK) continue;
        #pragma unroll
        for (int j = 0; j < 4; j++)
            out[((size_t)b * NTOK + qr) * EMB + hh * HD + tx*4 + j] = acc[i][j];
    }
}

// ---------------- fused residual add + LayerNorm ----------------------------
__global__ __launch_bounds__(256)
void add_ln(const float* __restrict__ a, const float* __restrict__ b,
            const float* __restrict__ g, const float* __restrict__ be,
            float* __restrict__ out)
{
    const int r   = blockIdx.x;
    const int tid = threadIdx.x;
    float v[3];
    float s = 0.f, q = 0.f;
    #pragma unroll
    for (int t = 0; t < 3; t++) {
        int c = tid + t * 256;
        v[t] = a[(size_t)r * EMB + c] + b[(size_t)r * EMB + c];
        s += v[t];
        q += v[t] * v[t];
    }
    #pragma unroll
    for (int o = 16; o; o >>= 1) {
        s += __shfl_xor_sync(0xffffffffu, s, o);
        q += __shfl_xor_sync(0xffffffffu, q, o);
    }
    __shared__ float red[2][8];
    int w = tid >> 5, lane = tid & 31;
    if (lane == 0) { red[0][w] = s; red[1][w] = q; }
    __syncthreads();
    s = 0.f; q = 0.f;
    #pragma unroll
    for (int i = 0; i < 8; i++) { s += red[0][i]; q += red[1][i]; }
    float mean = s * (1.f / EMB);
    float var  = q * (1.f / EMB) - mean * mean;
    float rstd = rsqrtf(var + EPS);
    #pragma unroll
    for (int t = 0; t < 3; t++) {
        int c = tid + t * 256;
        out[(size_t)r * EMB + c] = (v[t] - mean) * rstd * g[c] + be[c];
    }
}

// LN of the 32 cls rows (stride NTOK*EMB apart)
__global__ __launch_bounds__(256)
void cls_ln(const float* __restrict__ h, const float* __restrict__ g,
            const float* __restrict__ be, float* __restrict__ out)
{
    const int b   = blockIdx.x;
    const int tid = threadIdx.x;
    const float* row = h + (size_t)b * NTOK * EMB;
    float v[3];
    float s = 0.f, q = 0.f;
    #pragma unroll
    for (int t = 0; t < 3; t++) {
        int c = tid + t * 256;
        v[t] = row[c];
        s += v[t];
        q += v[t] * v[t];
    }
    #pragma unroll
    for (int o = 16; o; o >>= 1) {
        s += __shfl_xor_sync(0xffffffffu, s, o);
        q += __shfl_xor_sync(0xffffffffu, q, o);
    }
    __shared__ float red[2][8];
    int w = tid >> 5, lane = tid & 31;
    if (lane == 0) { red[0][w] = s; red[1][w] = q; }
    __syncthreads();
    s = 0.f; q = 0.f;
    #pragma unroll
    for (int i = 0; i < 8; i++) { s += red[0][i]; q += red[1][i]; }
    float mean = s * (1.f / EMB);
    float var  = q * (1.f / EMB) - mean * mean;
    float rstd = rsqrtf(var + EPS);
    #pragma unroll
    for (int t = 0; t < 3; t++) {
        int c = tid + t * 256;
        out[(size_t)b * EMB + c] = (v[t] - mean) * rstd * g[c] + be[c];
    }
}

// ---------------- classifier head -------------------------------------------
__global__ __launch_bounds__(256)
void head_gemm(const float* __restrict__ cls, const float* __restrict__ W,
               const float* __restrict__ bias, float* __restrict__ out)
{
    int idx = blockIdx.x * blockDim.x + threadIdx.x;
    if (idx >= BATCH * NCLS) return;
    int b = idx / NCLS;
    int n = idx % NCLS;
    float s = bias[n];
    const float* c = cls + (size_t)b * EMB;
    for (int k = 0; k < EMB; k++)
        s = fmaf(c[k], W[(size_t)k * NCLS + n], s);
    out[idx] = s;
}

// ---------------- driver -----------------------------------------------------
extern "C" void kernel_launch(void* const* d_in, const int* in_sizes, int n_in,
                              void* d_out, int out_size)
{
    const float* x        = (const float*)d_in[0];
    const float* conv_w   = (const float*)d_in[1];
    const float* conv_b   = (const float*)d_in[2];
    const float* cls_tok  = (const float*)d_in[3];
    const float* pos_emb  = (const float*)d_in[4];
    const float* Wq       = (const float*)d_in[5];
    const float* Wk       = (const float*)d_in[6];
    const float* Wv       = (const float*)d_in[7];
    const float* Wo       = (const float*)d_in[8];
    const float* bo       = (const float*)d_in[9];
    const float* ln1_g    = (const float*)d_in[10];
    const float* ln1_b    = (const float*)d_in[11];
    const float* W1       = (const float*)d_in[12];
    const float* b1       = (const float*)d_in[13];
    const float* W2       = (const float*)d_in[14];
    const float* b2       = (const float*)d_in[15];
    const float* ln2_g    = (const float*)d_in[16];
    const float* ln2_b    = (const float*)d_in[17];
    const float* head_g   = (const float*)d_in[18];
    const float* head_b   = (const float*)d_in[19];
    const float* head_W   = (const float*)d_in[20];
    const float* head_bias= (const float*)d_in[21];
    float* out = (float*)d_out;

    float *ph, *pq, *pk, *pv, *pt, *px, *pff, *psc, *pim, *pwt, *pcls;
    cudaGetSymbolAddress((void**)&ph,  g_h);
    cudaGetSymbolAddress((void**)&pq,  g_q);
    cudaGetSymbolAddress((void**)&pk,  g_k);
    cudaGetSymbolAddress((void**)&pv,  g_v);
    cudaGetSymbolAddress((void**)&pt,  g_t);
    cudaGetSymbolAddress((void**)&px,  g_x);
    cudaGetSymbolAddress((void**)&pff, g_ff);
    cudaGetSymbolAddress((void**)&psc, g_sc);
    cudaGetSymbolAddress((void**)&pim, g_im);
    cudaGetSymbolAddress((void**)&pwt, g_wt);
    cudaGetSymbolAddress((void**)&pcls,g_cls);

    // ---- patch embedding ----
    transpose_w<<<(EMB*EMB + 255)/256, 256>>>(conv_w, pwt);
    im2col_kernel<<<(PROWS*EMB + 255)/256, 256>>>(x, pim);
    {
        dim3 g(EMB/BN, (PROWS + BM - 1)/BM);
        gemm_nn<<<g, 256>>>(pim, pwt, conv_b, pt, PROWS, EMB, EMB, 0);
    }
    embed_kernel<<<(ROWS*EMB + 255)/256, 256>>>(pt, cls_tok, pos_emb, ph);

    const dim3 gE(EMB/BN,  (ROWS + BM - 1)/BM);   // 6 x 50
    const dim3 gF1(FF/BN,  (ROWS + BM - 1)/BM);   // 24 x 50
    const dim3 gS(7, 7, BATCH*NHEAD);
    const dim3 gA(7, BATCH*NHEAD);
    const int  smrows = BATCH*NHEAD*NTOK;

    for (int l = 0; l < DEPTH; l++) {
        const float* wq = Wq + (size_t)l*EMB*EMB;
        const float* wk = Wk + (size_t)l*EMB*EMB;
        const float* wv = Wv + (size_t)l*EMB*EMB;
        const float* wo = Wo + (size_t)l*EMB*EMB;
        const float* bol= bo + (size_t)l*EMB;
        const float* g1 = ln1_g + (size_t)l*EMB;
        const float* be1= ln1_b + (size_t)l*EMB;
        const float* w1 = W1 + (size_t)l*EMB*FF;
        const float* bb1= b1 + (size_t)l*FF;
        const float* w2 = W2 + (size_t)l*FF*EMB;
        const float* bb2= b2 + (size_t)l*EMB;
        const float* g2 = ln2_g + (size_t)l*EMB;
        const float* be2= ln2_b + (size_t)l*EMB;

        gemm_nn<<<gE, 256>>>(ph, wq, nullptr, pq, ROWS, EMB, EMB, 0);
        gemm_nn<<<gE, 256>>>(ph, wk, nullptr, pk, ROWS, EMB, EMB, 0);
        gemm_nn<<<gE, 256>>>(ph, wv, nullptr, pv, ROWS, EMB, EMB, 0);

        attn_scores<<<gS, 256>>>(pq, pk, psc);
        softmax_kernel<<<(smrows + 7)/8, 256>>>(psc, smrows);
        attn_av<<<gA, 256>>>(psc, pv, pt);

        gemm_nn<<<gE, 256>>>(pt, wo, bol, pq, ROWS, EMB, EMB, 0);   // reuse pq
        add_ln<<<ROWS, 256>>>(pq, ph, g1, be1, px);

        gemm_nn<<<gF1, 256>>>(px, w1, bb1, pff, ROWS, FF, EMB, 1);  // relu
        gemm_nn<<<gE, 256>>>(pff, w2, bb2, pt, ROWS, EMB, FF, 0);
        add_ln<<<ROWS, 256>>>(pt, px, g2, be2, ph);
    }

    cls_ln<<<BATCH, 256>>>(ph, head_g, head_b, pcls);
    head_gemm<<<(BATCH*NCLS + 255)/256, 256>>>(pcls, head_W, head_bias, out);
}

// round 3
// speedup vs baseline: 1.9122x; 1.9122x over previous
#include <cuda_runtime.h>
#include <cuda_bf16.h>
#include <cstdint>
#include <cstddef>

// ---------------- Problem constants ----------------
#define IMG   224
#define PATCH 16
#define EMB   768
#define DEPTH 12
#define NHEAD 12
#define HD    64
#define FF    3072
#define NCLS  1000
#define BATCH 32
#define NP    196
#define NTOK  197
#define ROWS  (BATCH * NTOK) // 6304
#define PROWS (BATCH * NP)   // 6272
#define EPS   1e-5f

// weight-split layout (per layer, element offsets)
#define OFF_Q   0
#define OFF_K   589824
#define OFF_V   1179648
#define OFF_O   1769472
#define OFF_W1  2359296
#define OFF_W2  4718592
#define LSTRIDE 7077888
#define WTOTAL  (LSTRIDE * DEPTH)

// ---------------- Scratch ----------------
__device__ float g_h  [ROWS * EMB];
__device__ float g_q  [ROWS * EMB];
__device__ float g_k  [ROWS * EMB];
__device__ float g_v  [ROWS * EMB];
__device__ float g_t  [ROWS * EMB];
__device__ float g_x  [ROWS * EMB];
__device__ float g_ff [ROWS * FF];
__device__ float g_sc [(size_t)BATCH * NHEAD * NTOK * NTOK];
__device__ float g_im [PROWS * EMB];
__device__ float g_cls[BATCH * EMB];
__device__ __nv_bfloat16 g_whi[WTOTAL];
__device__ __nv_bfloat16 g_wlo[WTOTAL];
__device__ __nv_bfloat16 g_cwhi[EMB * EMB];
__device__ __nv_bfloat16 g_cwlo[EMB * EMB];

// ---------------- warp-MMA helpers (sm_80-compatible PTX) -------------------
__device__ __forceinline__ uint32_t smem_u32(const void* p) {
    uint32_t a;
    asm("{ .reg .u64 t; cvta.to.shared.u64 t, %1; cvt.u32.u64 %0, t; }"
        : "=r"(a) : "l"(p));
    return a;
}

__device__ __forceinline__ void ldm_x4(uint32_t (&r)[4], uint32_t addr) {
    asm volatile("ldmatrix.sync.aligned.m8n8.x4.shared.b16 {%0,%1,%2,%3}, [%4];"
                 : "=r"(r[0]), "=r"(r[1]), "=r"(r[2]), "=r"(r[3]) : "r"(addr));
}

__device__ __forceinline__ void mma_bf16(float (&d)[4], const uint32_t (&a)[4],
                                         const uint32_t (&b)[2]) {
    asm volatile("mma.sync.aligned.m16n8k16.row.col.f32.bf16.bf16.f32 "
                 "{%0,%1,%2,%3}, {%4,%5,%6,%7}, {%8,%9}, {%0,%1,%2,%3};"
                 : "+f"(d[0]), "+f"(d[1]), "+f"(d[2]), "+f"(d[3])
                 : "r"(a[0]), "r"(a[1]), "r"(a[2]), "r"(a[3]),
                   "r"(b[0]), "r"(b[1]));
}

// ---------------- weight prep: transpose [K,N] -> [N,K] + bf16 hi/lo split ---
__global__ void transpose_split(const float* __restrict__ W,
                                __nv_bfloat16* __restrict__ hi,
                                __nv_bfloat16* __restrict__ lo,
                                int K, int N)
{
    __shared__ float t[32][33];
    int nb = blockIdx.x * 32, kb = blockIdx.y * 32;
    int tx = threadIdx.x, ty = threadIdx.y;
    #pragma unroll
    for (int j = ty; j < 32; j += 8)
        t[j][tx] = W[(size_t)(kb + j) * N + nb + tx];
    __syncthreads();
    #pragma unroll
    for (int j = ty; j < 32; j += 8) {
        float x = t[tx][j];
        __nv_bfloat16 h = __float2bfloat16(x);
        __nv_bfloat16 l = __float2bfloat16(x - __bfloat162float(h));
        size_t o = (size_t)(nb + j) * K + kb + tx;
        hi[o] = h; lo[o] = l;
    }
}

__global__ void split_only(const float* __restrict__ W,
                           __nv_bfloat16* __restrict__ hi,
                           __nv_bfloat16* __restrict__ lo, int n)
{
    int i = blockIdx.x * blockDim.x + threadIdx.x;
    if (i >= n) return;
    float x = W[i];
    __nv_bfloat16 h = __float2bfloat16(x);
    hi[i] = h;
    lo[i] = __float2bfloat16(x - __bfloat162float(h));
}

// ---------------- HMMA GEMM: C[M,N] = A[M,K](f32) @ Wt[N,K]^T (bf16 hi/lo) ---
#define BM 128
#define BN 128
#define BK 32
#define LDS_PAD 8
#define LDA (BK + LDS_PAD)   // 40 bf16 elements per smem row

__global__ __launch_bounds__(256)
void gemm_hmma(const float* __restrict__ A,
               const __nv_bfloat16* __restrict__ Bhi,
               const __nv_bfloat16* __restrict__ Blo,
               const float* __restrict__ bias,
               float* __restrict__ C,
               int M, int N, int K, int do_relu)
{
    __shared__ __align__(16) __nv_bfloat16 sAh[BM * LDA];
    __shared__ __align__(16) __nv_bfloat16 sAl[BM * LDA];
    __shared__ __align__(16) __nv_bfloat16 sBh[BN * LDA];
    __shared__ __align__(16) __nv_bfloat16 sBl[BN * LDA];

    const int tid  = threadIdx.x;
    const int lane = tid & 31;
    const int wid  = tid >> 5;
    const int wm   = wid & 1;   // 2 warp rows of 64
    const int wn   = wid >> 1;  // 4 warp cols of 32
    const int row0 = blockIdx.y * BM;
    const int col0 = blockIdx.x * BN;

    const uint32_t uAh = smem_u32(sAh);
    const uint32_t uAl = smem_u32(sAl);
    const uint32_t uBh = smem_u32(sBh);
    const uint32_t uBl = smem_u32(sBl);

    float acc[4][4][4];
    #pragma unroll
    for (int i = 0; i < 4; i++)
        #pragma unroll
        for (int j = 0; j < 4; j++)
            #pragma unroll
            for (int c = 0; c < 4; c++) acc[i][j][c] = 0.f;

    // load index precompute: 1024 slots (A: float4, B: uint2 of 4 bf16)
    const int lr  = tid >> 1;            // A/B row pair base: 2 threads per row? no:
    // A: idx in [0,1024): r=idx>>3 (0..127), c4=(idx&7)*4
    for (int kt = 0; kt < K; kt += BK) {
        // ---- global loads into registers ----
        float4 av[4];
        uint2  bhv[4], blv[4];
        #pragma unroll
        for (int l = 0; l < 4; l++) {
            int idx = tid + l * 256;
            int r   = idx >> 3;
            int c4  = (idx & 7) << 2;
            int gr  = row0 + r;
            av[l] = make_float4(0.f, 0.f, 0.f, 0.f);
            if (gr < M)
                av[l] = *reinterpret_cast<const float4*>(&A[(size_t)gr * K + kt + c4]);
            size_t gb = (size_t)(col0 + r) * K + kt + c4;
            bhv[l] = *reinterpret_cast<const uint2*>(&Bhi[gb]);
            blv[l] = *reinterpret_cast<const uint2*>(&Blo[gb]);
        }

        __syncthreads();   // previous compute done

        #pragma unroll
        for (int l = 0; l < 4; l++) {
            int idx = tid + l * 256;
            int r   = idx >> 3;
            int c4  = (idx & 7) << 2;
            float4 v = av[l];
            __nv_bfloat16 h0 = __float2bfloat16(v.x);
            __nv_bfloat16 h1 = __float2bfloat16(v.y);
            __nv_bfloat16 h2 = __float2bfloat16(v.z);
            __nv_bfloat16 h3 = __float2bfloat16(v.w);
            __nv_bfloat16 l0 = __float2bfloat16(v.x - __bfloat162float(h0));
            __nv_bfloat16 l1 = __float2bfloat16(v.y - __bfloat162float(h1));
            __nv_bfloat16 l2 = __float2bfloat16(v.z - __bfloat162float(h2));
            __nv_bfloat16 l3 = __float2bfloat16(v.w - __bfloat162float(h3));
            uint32_t hA = (uint32_t)__bfloat16_as_ushort(h0)
                        | ((uint32_t)__bfloat16_as_ushort(h1) << 16);
            uint32_t hB = (uint32_t)__bfloat16_as_ushort(h2)
                        | ((uint32_t)__bfloat16_as_ushort(h3) << 16);
            uint32_t lA = (uint32_t)__bfloat16_as_ushort(l0)
                        | ((uint32_t)__bfloat16_as_ushort(l1) << 16);
            uint32_t lB = (uint32_t)__bfloat16_as_ushort(l2)
                        | ((uint32_t)__bfloat16_as_ushort(l3) << 16);
            int o = r * LDA + c4;
            *reinterpret_cast<uint2*>(&sAh[o]) = make_uint2(hA, hB);
            *reinterpret_cast<uint2*>(&sAl[o]) = make_uint2(lA, lB);
            *reinterpret_cast<uint2*>(&sBh[o]) = bhv[l];
            *reinterpret_cast<uint2*>(&sBl[o]) = blv[l];
        }

        __syncthreads();

        // ---- compute: 2 k16 steps ----
        #pragma unroll
        for (int kk = 0; kk < 2; kk++) {
            const int kc = kk * 16 + ((lane >> 4) << 3);
            uint32_t a_hi[4][4], a_lo[4][4];
            uint32_t b_hi[4][2], b_lo[4][2];
            #pragma unroll
            for (int mi = 0; mi < 4; mi++) {
                uint32_t off = ((wm * 64 + mi * 16 + (lane & 15)) * LDA + kc) * 2;
                ldm_x4(a_hi[mi], uAh + off);
                ldm_x4(a_lo[mi], uAl + off);
            }
            #pragma unroll
            for (int g = 0; g < 2; g++) {
                uint32_t off = ((wn * 32 + g * 16 + (lane & 15)) * LDA + kc) * 2;
                uint32_t th[4], tl[4];
                ldm_x4(th, uBh + off);
                ldm_x4(tl, uBl + off);
                b_hi[g*2+0][0] = th[0]; b_hi[g*2+0][1] = th[2];
                b_hi[g*2+1][0] = th[1]; b_hi[g*2+1][1] = th[3];
                b_lo[g*2+0][0] = tl[0]; b_lo[g*2+0][1] = tl[2];
                b_lo[g*2+1][0] = tl[1]; b_lo[g*2+1][1] = tl[3];
            }
            #pragma unroll
            for (int mi = 0; mi < 4; mi++)
                #pragma unroll
                for (int n = 0; n < 4; n++) {
                    mma_bf16(acc[mi][n], a_hi[mi], b_hi[n]);
                    mma_bf16(acc[mi][n], a_hi[mi], b_lo[n]);
                    mma_bf16(acc[mi][n], a_lo[mi], b_hi[n]);
                }
        }
    }

    // ---- epilogue ----
    const bool hb = (bias != nullptr);
    #pragma unroll
    for (int mi = 0; mi < 4; mi++) {
        #pragma unroll
        for (int n = 0; n < 4; n++) {
            int gc = col0 + wn * 32 + n * 8 + (lane & 3) * 2;
            float bx = 0.f, by = 0.f;
            if (hb) { bx = bias[gc]; by = bias[gc + 1]; }
            #pragma unroll
            for (int h = 0; h < 2; h++) {
                int gr = row0 + wm * 64 + mi * 16 + (lane >> 2) + h * 8;
                if (gr >= M) continue;
                float2 o;
                o.x = acc[mi][n][h * 2 + 0] + bx;
                o.y = acc[mi][n][h * 2 + 1] + by;
                if (do_relu) { o.x = fmaxf(o.x, 0.f); o.y = fmaxf(o.y, 0.f); }
                *reinterpret_cast<float2*>(&C[(size_t)gr * N + gc]) = o;
            }
        }
    }
}

// ---------------- im2col ----------------
__global__ void im2col_kernel(const float* __restrict__ x, float* __restrict__ out)
{
    int idx = blockIdx.x * blockDim.x + threadIdx.x;
    if (idx >= PROWS * EMB) return;
    int row = idx / EMB;
    int k   = idx % EMB;
    int b   = row / NP;
    int p   = row % NP;
    int py  = p / 14, px = p % 14;
    int c   = k / 256;
    int r2  = k % 256;
    int ph  = r2 / PATCH, pw = r2 % PATCH;
    out[idx] = x[(((size_t)b * 3 + c) * IMG + (py * PATCH + ph)) * IMG
                 + (px * PATCH + pw)];
}

__global__ void embed_kernel(const float* __restrict__ patch,
                             const float* __restrict__ cls_tok,
                             const float* __restrict__ pos,
                             float* __restrict__ h)
{
    int idx = blockIdx.x * blockDim.x + threadIdx.x;
    if (idx >= ROWS * EMB) return;
    int row = idx / EMB;
    int e   = idx % EMB;
    int b   = row / NTOK;
    int n   = row % NTOK;
    float base = (n == 0) ? cls_tok[e]
                          : patch[((size_t)b * NP + (n - 1)) * EMB + e];
    h[idx] = base + pos[n * EMB + e];
}

// ---------------- attention (fp32 SIMT) --------------------------------------
__global__ __launch_bounds__(256)
void attn_scores(const float* __restrict__ q, const float* __restrict__ k,
                 float* __restrict__ scores)
{
    const int bh = blockIdx.z;
    const int b  = bh / NHEAD;
    const int hh = bh % NHEAD;
    const int q0 = blockIdx.y * 32;
    const int k0 = blockIdx.x * 32;
    const float scale = 0.036084391824f;

    __shared__ __align__(16) float Qs[32][65];
    __shared__ __align__(16) float Ks[32][65];

    const int tid = threadIdx.x;
    const float* Qb = q + (size_t)b * NTOK * EMB + hh * HD;
    const float* Kb = k + (size_t)b * NTOK * EMB + hh * HD;

    #pragma unroll
    for (int l = 0; l < 2; l++) {
        int idx = tid + l * 256;
        int r   = idx >> 4;
        int c4  = (idx & 15) << 2;
        float4 vq = make_float4(0.f,0.f,0.f,0.f);
        float4 vk = make_float4(0.f,0.f,0.f,0.f);
        if (q0 + r < NTOK)
            vq = *reinterpret_cast<const float4*>(&Qb[(size_t)(q0 + r) * EMB + c4]);
        if (k0 + r < NTOK)
            vk = *reinterpret_cast<const float4*>(&Kb[(size_t)(k0 + r) * EMB + c4]);
        Qs[r][c4+0]=vq.x; Qs[r][c4+1]=vq.y; Qs[r][c4+2]=vq.z; Qs[r][c4+3]=vq.w;
        Ks[r][c4+0]=vk.x; Ks[r][c4+1]=vk.y; Ks[r][c4+2]=vk.z; Ks[r][c4+3]=vk.w;
    }
    __syncthreads();

    const int tx = tid & 15;
    const int ty = tid >> 4;
    float acc[2][2] = {{0.f,0.f},{0.f,0.f}};
    #pragma unroll
    for (int kk = 0; kk < HD; kk++) {
        float a0 = Qs[ty*2+0][kk], a1 = Qs[ty*2+1][kk];
        float b0 = Ks[tx*2+0][kk], b1 = Ks[tx*2+1][kk];
        acc[0][0] = fmaf(a0,b0,acc[0][0]);
        acc[0][1] = fmaf(a0,b1,acc[0][1]);
        acc[1][0] = fmaf(a1,b0,acc[1][0]);
        acc[1][1] = fmaf(a1,b1,acc[1][1]);
    }
    #pragma unroll
    for (int i = 0; i < 2; i++) {
        int qr = q0 + ty*2 + i;
        if (qr >= NTOK) continue;
        #pragma unroll
        for (int j = 0; j < 2; j++) {
            int kc = k0 + tx*2 + j;
            if (kc >= NTOK) continue;
            scores[((size_t)bh * NTOK + qr) * NTOK + kc] = acc[i][j] * scale;
        }
    }
}

__global__ __launch_bounds__(256)
void softmax_kernel(float* __restrict__ scores, int nrows)
{
    int row = blockIdx.x * 8 + (threadIdx.x >> 5);
    if (row >= nrows) return;
    int lane = threadIdx.x & 31;
    float* p = scores + (size_t)row * NTOK;

    float vals[7];
    float mx = -1e30f;
    #pragma unroll
    for (int i = 0; i < 7; i++) {
        int c = i * 32 + lane;
        vals[i] = (c < NTOK) ? p[c] : -1e30f;
        mx = fmaxf(mx, vals[i]);
    }
    #pragma unroll
    for (int o = 16; o; o >>= 1) mx = fmaxf(mx, __shfl_xor_sync(0xffffffffu, mx, o));

    float s = 0.f;
    #pragma unroll
    for (int i = 0; i < 7; i++) {
        vals[i] = expf(vals[i] - mx);
        s += vals[i];
    }
    #pragma unroll
    for (int o = 16; o; o >>= 1) s += __shfl_xor_sync(0xffffffffu, s, o);
    float inv = 1.f / s;
    #pragma unroll
    for (int i = 0; i < 7; i++) {
        int c = i * 32 + lane;
        if (c < NTOK) p[c] = vals[i] * inv;
    }
}

__global__ __launch_bounds__(256)
void attn_av(const float* __restrict__ attn, const float* __restrict__ v,
             float* __restrict__ out)
{
    const int bh = blockIdx.y;
    const int b  = bh / NHEAD;
    const int hh = bh % NHEAD;
    const int q0 = blockIdx.x * 32;

    __shared__ __align__(16) float As[32][33];
    __shared__ __align__(16) float Vs[32][64];

    const int tid = threadIdx.x;
    const int tx  = tid & 15;
    const int ty  = tid >> 4;
    const float* Arow = attn + (size_t)bh * NTOK * NTOK;
    const float* Vb   = v + (size_t)b * NTOK * EMB + hh * HD;

    float acc[2][4] = {};

    for (int kt = 0; kt < NTOK; kt += 32) {
        {
            int base = tid * 4;
            int r = base >> 5;
            int c = base & 31;
            #pragma unroll
            for (int u = 0; u < 4; u++) {
                int qr = q0 + r, kc = kt + c + u;
                As[r][c + u] = (qr < NTOK && kc < NTOK)
                               ? Arow[(size_t)qr * NTOK + kc] : 0.f;
            }
        }
        #pragma unroll
        for (int l = 0; l < 2; l++) {
            int idx = tid + l * 256;
            int r   = idx >> 4;
            int c4  = (idx & 15) << 2;
            float4 val = make_float4(0.f,0.f,0.f,0.f);
            if (kt + r < NTOK)
                val = *reinterpret_cast<const float4*>(&Vb[(size_t)(kt + r) * EMB + c4]);
            *reinterpret_cast<float4*>(&Vs[r][c4]) = val;
        }
        __syncthreads();

        #pragma unroll
        for (int kk = 0; kk < 32; kk++) {
            float a0 = As[ty*2+0][kk];
            float a1 = As[ty*2+1][kk];
            float rb[4];
            *reinterpret_cast<float4*>(rb) =
                *reinterpret_cast<const float4*>(&Vs[kk][tx*4]);
            #pragma unroll
            for (int j = 0; j < 4; j++) {
                acc[0][j] = fmaf(a0, rb[j], acc[0][j]);
                acc[1][j] = fmaf(a1, rb[j], acc[1][j]);
            }
        }
        __syncthreads();
    }

    #pragma unroll
    for (int i = 0; i < 2; i++) {
        int qr = q0 + ty*2 + i;
        if (qr >= NTOK) continue;
        #pragma unroll
        for (int j = 0; j < 4; j++)
            out[((size_t)b * NTOK + qr) * EMB + hh * HD + tx*4 + j] = acc[i][j];
    }
}

// ---------------- fused residual add + LayerNorm ----------------------------
__global__ __launch_bounds__(256)
void add_ln(const float* __restrict__ a, const float* __restrict__ b,
            const float* __restrict__ g, const float* __restrict__ be,
            float* __restrict__ out)
{
    const int r   = blockIdx.x;
    const int tid = threadIdx.x;
    float v[3];
    float s = 0.f, q = 0.f;
    #pragma unroll
    for (int t = 0; t < 3; t++) {
        int c = tid + t * 256;
        v[t] = a[(size_t)r * EMB + c] + b[(size_t)r * EMB + c];
        s += v[t];
        q += v[t] * v[t];
    }
    #pragma unroll
    for (int o = 16; o; o >>= 1) {
        s += __shfl_xor_sync(0xffffffffu, s, o);
        q += __shfl_xor_sync(0xffffffffu, q, o);
    }
    __shared__ float red[2][8];
    int w = tid >> 5, lane = tid & 31;
    if (lane == 0) { red[0][w] = s; red[1][w] = q; }
    __syncthreads();
    s = 0.f; q = 0.f;
    #pragma unroll
    for (int i = 0; i < 8; i++) { s += red[0][i]; q += red[1][i]; }
    float mean = s * (1.f / EMB);
    float var  = q * (1.f / EMB) - mean * mean;
    float rstd = rsqrtf(var + EPS);
    #pragma unroll
    for (int t = 0; t < 3; t++) {
        int c = tid + t * 256;
        out[(size_t)r * EMB + c] = (v[t] - mean) * rstd * g[c] + be[c];
    }
}

__global__ __launch_bounds__(256)
void cls_ln(const float* __restrict__ h, const float* __restrict__ g,
            const float* __restrict__ be, float* __restrict__ out)
{
    const int b   = blockIdx.x;
    const int tid = threadIdx.x;
    const float* row = h + (size_t)b * NTOK * EMB;
    float v[3];
    float s = 0.f, q = 0.f;
    #pragma unroll
    for (int t = 0; t < 3; t++) {
        int c = tid + t * 256;
        v[t] = row[c];
        s += v[t];
        q += v[t] * v[t];
    }
    #pragma unroll
    for (int o = 16; o; o >>= 1) {
        s += __shfl_xor_sync(0xffffffffu, s, o);
        q += __shfl_xor_sync(0xffffffffu, q, o);
    }
    __shared__ float red[2][8];
    int w = tid >> 5, lane = tid & 31;
    if (lane == 0) { red[0][w] = s; red[1][w] = q; }
    __syncthreads();
    s = 0.f; q = 0.f;
    #pragma unroll
    for (int i = 0; i < 8; i++) { s += red[0][i]; q += red[1][i]; }
    float mean = s * (1.f / EMB);
    float var  = q * (1.f / EMB) - mean * mean;
    float rstd = rsqrtf(var + EPS);
    #pragma unroll
    for (int t = 0; t < 3; t++) {
        int c = tid + t * 256;
        out[(size_t)b * EMB + c] = (v[t] - mean) * rstd * g[c] + be[c];
    }
}

// ---------------- classifier head -------------------------------------------
__global__ __launch_bounds__(256)
void head_gemm(const float* __restrict__ cls, const float* __restrict__ W,
               const float* __restrict__ bias, float* __restrict__ out)
{
    int idx = blockIdx.x * blockDim.x + threadIdx.x;
    if (idx >= BATCH * NCLS) return;
    int b = idx / NCLS;
    int n = idx % NCLS;
    float s = bias[n];
    const float* c = cls + (size_t)b * EMB;
    for (int k = 0; k < EMB; k++)
        s = fmaf(c[k], W[(size_t)k * NCLS + n], s);
    out[idx] = s;
}

// ---------------- driver -----------------------------------------------------
extern "C" void kernel_launch(void* const* d_in, const int* in_sizes, int n_in,
                              void* d_out, int out_size)
{
    const float* x        = (const float*)d_in[0];
    const float* conv_w   = (const float*)d_in[1];
    const float* conv_b   = (const float*)d_in[2];
    const float* cls_tok  = (const float*)d_in[3];
    const float* pos_emb  = (const float*)d_in[4];
    const float* Wq       = (const float*)d_in[5];
    const float* Wk       = (const float*)d_in[6];
    const float* Wv       = (const float*)d_in[7];
    const float* Wo       = (const float*)d_in[8];
    const float* bo       = (const float*)d_in[9];
    const float* ln1_g    = (const float*)d_in[10];
    const float* ln1_b    = (const float*)d_in[11];
    const float* W1       = (const float*)d_in[12];
    const float* b1       = (const float*)d_in[13];
    const float* W2       = (const float*)d_in[14];
    const float* b2       = (const float*)d_in[15];
    const float* ln2_g    = (const float*)d_in[16];
    const float* ln2_b    = (const float*)d_in[17];
    const float* head_g   = (const float*)d_in[18];
    const float* head_b   = (const float*)d_in[19];
    const float* head_W   = (const float*)d_in[20];
    const float* head_bias= (const float*)d_in[21];
    float* out = (float*)d_out;

    float *ph, *pq, *pk, *pv, *pt, *px, *pff, *psc, *pim, *pcls;
    __nv_bfloat16 *pwhi, *pwlo, *pcwhi, *pcwlo;
    cudaGetSymbolAddress((void**)&ph,   g_h);
    cudaGetSymbolAddress((void**)&pq,   g_q);
    cudaGetSymbolAddress((void**)&pk,   g_k);
    cudaGetSymbolAddress((void**)&pv,   g_v);
    cudaGetSymbolAddress((void**)&pt,   g_t);
    cudaGetSymbolAddress((void**)&px,   g_x);
    cudaGetSymbolAddress((void**)&pff,  g_ff);
    cudaGetSymbolAddress((void**)&psc,  g_sc);
    cudaGetSymbolAddress((void**)&pim,  g_im);
    cudaGetSymbolAddress((void**)&pcls, g_cls);
    cudaGetSymbolAddress((void**)&pwhi, g_whi);
    cudaGetSymbolAddress((void**)&pwlo, g_wlo);
    cudaGetSymbolAddress((void**)&pcwhi,g_cwhi);
    cudaGetSymbolAddress((void**)&pcwlo,g_cwlo);

    // ---- weight prep: transpose + bf16 hi/lo split ----
    {
        dim3 blk(32, 8);
        for (int l = 0; l < DEPTH; l++) {
            size_t base = (size_t)l * LSTRIDE;
            dim3 gEE(EMB/32, EMB/32);
            transpose_split<<<gEE, blk>>>(Wq + (size_t)l*EMB*EMB, pwhi + base + OFF_Q, pwlo + base + OFF_Q, EMB, EMB);
            transpose_split<<<gEE, blk>>>(Wk + (size_t)l*EMB*EMB, pwhi + base + OFF_K, pwlo + base + OFF_K, EMB, EMB);
            transpose_split<<<gEE, blk>>>(Wv + (size_t)l*EMB*EMB, pwhi + base + OFF_V, pwlo + base + OFF_V, EMB, EMB);
            transpose_split<<<gEE, blk>>>(Wo + (size_t)l*EMB*EMB, pwhi + base + OFF_O, pwlo + base + OFF_O, EMB, EMB);
            dim3 g1(FF/32, EMB/32);   // W1: [K=768, N=3072]
            transpose_split<<<g1, blk>>>(W1 + (size_t)l*EMB*FF, pwhi + base + OFF_W1, pwlo + base + OFF_W1, EMB, FF);
            dim3 g2(EMB/32, FF/32);   // W2: [K=3072, N=768]
            transpose_split<<<g2, blk>>>(W2 + (size_t)l*FF*EMB, pwhi + base + OFF_W2, pwlo + base + OFF_W2, FF, EMB);
        }
        split_only<<<(EMB*EMB + 255)/256, 256>>>(conv_w, pcwhi, pcwlo, EMB*EMB);
    }

    // ---- patch embedding ----
    im2col_kernel<<<(PROWS*EMB + 255)/256, 256>>>(x, pim);
    gemm_hmma<<<dim3(EMB/BN, PROWS/BM), 256>>>(
        pim, pcwhi, pcwlo, conv_b, pt, PROWS, EMB, EMB, 0);
    embed_kernel<<<(ROWS*EMB + 255)/256, 256>>>(pt, cls_tok, pos_emb, ph);

    const int mtiles = (ROWS + BM - 1) / BM;   // 50
    const dim3 gE(EMB/BN,  mtiles);
    const dim3 gF1(FF/BN,  mtiles);
    const dim3 gS(7, 7, BATCH*NHEAD);
    const dim3 gA(7, BATCH*NHEAD);
    const int  smrows = BATCH*NHEAD*NTOK;

    for (int l = 0; l < DEPTH; l++) {
        size_t base = (size_t)l * LSTRIDE;
        const __nv_bfloat16* qh = pwhi + base + OFF_Q;
        const __nv_bfloat16* ql = pwlo + base + OFF_Q;
        const __nv_bfloat16* kh = pwhi + base + OFF_K;
        const __nv_bfloat16* kl = pwlo + base + OFF_K;
        const __nv_bfloat16* vh = pwhi + base + OFF_V;
        const __nv_bfloat16* vl = pwlo + base + OFF_V;
        const __nv_bfloat16* oh = pwhi + base + OFF_O;
        const __nv_bfloat16* ol = pwlo + base + OFF_O;
        const __nv_bfloat16* w1h= pwhi + base + OFF_W1;
        const __nv_bfloat16* w1l= pwlo + base + OFF_W1;
        const __nv_bfloat16* w2h= pwhi + base + OFF_W2;
        const __nv_bfloat16* w2l= pwlo + base + OFF_W2;
        const float* bol= bo + (size_t)l*EMB;
        const float* g1 = ln1_g + (size_t)l*EMB;
        const float* be1= ln1_b + (size_t)l*EMB;
        const float* bb1= b1 + (size_t)l*FF;
        const float* bb2= b2 + (size_t)l*EMB;
        const float* g2 = ln2_g + (size_t)l*EMB;
        const float* be2= ln2_b + (size_t)l*EMB;

        gemm_hmma<<<gE, 256>>>(ph, qh, ql, nullptr, pq, ROWS, EMB, EMB, 0);
        gemm_hmma<<<gE, 256>>>(ph, kh, kl, nullptr, pk, ROWS, EMB, EMB, 0);
        gemm_hmma<<<gE, 256>>>(ph, vh, vl, nullptr, pv, ROWS, EMB, EMB, 0);

        attn_scores<<<gS, 256>>>(pq, pk, psc);
        softmax_kernel<<<(smrows + 7)/8, 256>>>(psc, smrows);
        attn_av<<<gA, 256>>>(psc, pv, pt);

        gemm_hmma<<<gE, 256>>>(pt, oh, ol, bol, pq, ROWS, EMB, EMB, 0);
        add_ln<<<ROWS, 256>>>(pq, ph, g1, be1, px);

        gemm_hmma<<<gF1, 256>>>(px, w1h, w1l, bb1, pff, ROWS, FF, EMB, 1);
        gemm_hmma<<<gE,  256>>>(pff, w2h, w2l, bb2, pt, ROWS, EMB, FF, 0);
        add_ln<<<ROWS, 256>>>(pt, px, g2, be2, ph);
    }

    cls_ln<<<BATCH, 256>>>(ph, head_g, head_b, pcls);
    head_gemm<<<(BATCH*NCLS + 255)/256, 256>>>(pcls, head_W, head_bias, out);
}

// round 4
// speedup vs baseline: 2.0003x; 1.0460x over previous
#include <cuda_runtime.h>
#include <cuda_bf16.h>
#include <cstdint>
#include <cstddef>

// ---------------- Problem constants ----------------
#define IMG   224
#define PATCH 16
#define EMB   768
#define DEPTH 12
#define NHEAD 12
#define HD    64
#define FF    3072
#define NCLS  1000
#define BATCH 32
#define NP    196
#define NTOK  197
#define ROWS  (BATCH * NTOK) // 6304
#define PROWS (BATCH * NP)   // 6272
#define EPS   1e-5f
#define QS    2304           // fused qkv row stride

// weight-split layout (per layer, element offsets). Q,K,V contiguous -> fused.
#define OFF_Q   0
#define OFF_K   589824
#define OFF_V   1179648
#define OFF_O   1769472
#define OFF_W1  2359296
#define OFF_W2  4718592
#define LSTRIDE 7077888
#define WTOTAL  (LSTRIDE * DEPTH)

// ---------------- Scratch ----------------
__device__ float g_h  [ROWS * EMB];     // layer activation fp32
__device__ float g_x  [ROWS * EMB];     // post-LN1 fp32
__device__ float g_t  [ROWS * EMB];     // O-proj / conv out fp32
__device__ float g_qkv[ROWS * QS];      // fused qkv fp32
__device__ float g_sc [(size_t)BATCH * NHEAD * NTOK * NTOK];
__device__ float g_cls[BATCH * EMB];
__device__ __nv_bfloat16 g_hhi[ROWS * EMB],  g_hlo[ROWS * EMB];
__device__ __nv_bfloat16 g_xhi[ROWS * EMB],  g_xlo[ROWS * EMB];
__device__ __nv_bfloat16 g_thi[ROWS * EMB],  g_tlo[ROWS * EMB];
__device__ __nv_bfloat16 g_fhi[ROWS * FF],   g_flo[ROWS * FF];
__device__ __nv_bfloat16 g_imhi[PROWS * EMB], g_imlo[PROWS * EMB];
__device__ __nv_bfloat16 g_whi[WTOTAL], g_wlo[WTOTAL];
__device__ __nv_bfloat16 g_cwhi[EMB * EMB], g_cwlo[EMB * EMB];

// ---------------- helpers ----------------
__device__ __forceinline__ uint32_t smem_u32(const void* p) {
    uint32_t a;
    asm("{ .reg .u64 t; cvta.to.shared.u64 t, %1; cvt.u32.u64 %0, t; }"
        : "=r"(a) : "l"(p));
    return a;
}
__device__ __forceinline__ void ldm_x4(uint32_t (&r)[4], uint32_t addr) {
    asm volatile("ldmatrix.sync.aligned.m8n8.x4.shared.b16 {%0,%1,%2,%3}, [%4];"
                 : "=r"(r[0]), "=r"(r[1]), "=r"(r[2]), "=r"(r[3]) : "r"(addr));
}
__device__ __forceinline__ void mma_bf16(float (&d)[4], const uint32_t (&a)[4],
                                         const uint32_t (&b)[2]) {
    asm volatile("mma.sync.aligned.m16n8k16.row.col.f32.bf16.bf16.f32 "
                 "{%0,%1,%2,%3}, {%4,%5,%6,%7}, {%8,%9}, {%0,%1,%2,%3};"
                 : "+f"(d[0]), "+f"(d[1]), "+f"(d[2]), "+f"(d[3])
                 : "r"(a[0]), "r"(a[1]), "r"(a[2]), "r"(a[3]),
                   "r"(b[0]), "r"(b[1]));
}
__device__ __forceinline__ uint32_t pack_hi(float x, float y) {
    __nv_bfloat16 hx = __float2bfloat16(x), hy = __float2bfloat16(y);
    return (uint32_t)__bfloat16_as_ushort(hx)
         | ((uint32_t)__bfloat16_as_ushort(hy) << 16);
}
__device__ __forceinline__ uint32_t pack_lo(float x, float y) {
    __nv_bfloat16 hx = __float2bfloat16(x), hy = __float2bfloat16(y);
    __nv_bfloat16 lx = __float2bfloat16(x - __bfloat162float(hx));
    __nv_bfloat16 ly = __float2bfloat16(y - __bfloat162float(hy));
    return (uint32_t)__bfloat16_as_ushort(lx)
         | ((uint32_t)__bfloat16_as_ushort(ly) << 16);
}

// ---------------- weight prep (batched over layers) -------------------------
__global__ void transpose_split_batch(const float* __restrict__ W,
                                      __nv_bfloat16* __restrict__ hi,
                                      __nv_bfloat16* __restrict__ lo,
                                      int K, int N,
                                      size_t w_lstride, size_t o_lstride)
{
    __shared__ float t[32][33];
    const int layer = blockIdx.z;
    W  += (size_t)layer * w_lstride;
    hi += (size_t)layer * o_lstride;
    lo += (size_t)layer * o_lstride;
    int nb = blockIdx.x * 32, kb = blockIdx.y * 32;
    int tx = threadIdx.x, ty = threadIdx.y;
    #pragma unroll
    for (int j = ty; j < 32; j += 8)
        t[j][tx] = W[(size_t)(kb + j) * N + nb + tx];
    __syncthreads();
    #pragma unroll
    for (int j = ty; j < 32; j += 8) {
        float x = t[tx][j];
        __nv_bfloat16 h = __float2bfloat16(x);
        __nv_bfloat16 l = __float2bfloat16(x - __bfloat162float(h));
        size_t o = (size_t)(nb + j) * K + kb + tx;
        hi[o] = h; lo[o] = l;
    }
}

__global__ void split_only(const float* __restrict__ W,
                           __nv_bfloat16* __restrict__ hi,
                           __nv_bfloat16* __restrict__ lo, int n)
{
    int i = blockIdx.x * blockDim.x + threadIdx.x;
    if (i >= n) return;
    float x = W[i];
    __nv_bfloat16 h = __float2bfloat16(x);
    hi[i] = h;
    lo[i] = __float2bfloat16(x - __bfloat162float(h));
}

// ---------------- pipelined HMMA GEMM ----------------------------------------
// C[M,N] = A[M,K] @ B[N,K]^T, A/B in bf16 hi/lo (3-pass Markidis)
#define BM 128
#define BN 128
#define BK 32
#define LDA 40                      // bf16 elems per smem row (pad 8)
#define STAGE_B 40960               // 4 arrays * 128 * 40 * 2B
#define GEMM_SMEM (2 * STAGE_B)     // 80 KB

__global__ __launch_bounds__(256)
void gemm_hmma(const __nv_bfloat16* __restrict__ Ahi,
               const __nv_bfloat16* __restrict__ Alo,
               const __nv_bfloat16* __restrict__ Bhi,
               const __nv_bfloat16* __restrict__ Blo,
               const float* __restrict__ bias,
               float* __restrict__ Cf,
               __nv_bfloat16* __restrict__ Chi,
               __nv_bfloat16* __restrict__ Clo,
               int M, int N, int K, int do_relu)
{
    extern __shared__ __align__(16) unsigned char dsm[];
    const uint32_t smb = smem_u32(dsm);
    const int tid  = threadIdx.x;
    const int lane = tid & 31;
    const int wid  = tid >> 5;
    const int wm   = wid & 1;
    const int wn   = wid >> 1;
    const int row0 = blockIdx.y * BM;
    const int col0 = blockIdx.x * BN;

    float acc[4][4][4] = {};
    const __nv_bfloat16* srcs[4] = {Ahi, Alo, Bhi, Blo};

    auto load_stage = [&](int s, int kt) {
        #pragma unroll
        for (int l = 0; l < 8; l++) {
            int idx = tid + l * 256;
            int arr = idx >> 9;          // 0 Ah, 1 Al, 2 Bh, 3 Bl
            int w   = idx & 511;
            int r   = w >> 2;
            int q   = w & 3;
            int row = (arr < 2 ? row0 : col0) + r;
            const __nv_bfloat16* src = srcs[arr] + (size_t)row * K + kt + q * 8;
            int bytes = (arr < 2 && row >= M) ? 0 : 16;
            uint32_t dst = smb + (uint32_t)s * STAGE_B + (uint32_t)arr * 10240u
                         + (uint32_t)r * 80u + (uint32_t)q * 16u;
            asm volatile("cp.async.cg.shared.global [%0], [%1], 16, %2;"
                         :: "r"(dst), "l"(src), "r"(bytes) : "memory");
        }
        asm volatile("cp.async.commit_group;" ::: "memory");
    };

    auto compute_stage = [&](int s) {
        const uint32_t uAh = smb + (uint32_t)s * STAGE_B;
        const uint32_t uAl = uAh + 10240u;
        const uint32_t uBh = uAh + 20480u;
        const uint32_t uBl = uAh + 30720u;
        #pragma unroll
        for (int kk = 0; kk < 2; kk++) {
            const uint32_t kcb = (kk * 16 + ((lane >> 4) << 3)) * 2;
            uint32_t a_hi[4][4], a_lo[4][4];
            uint32_t b_hi[4][2], b_lo[4][2];
            #pragma unroll
            for (int mi = 0; mi < 4; mi++) {
                uint32_t off = (uint32_t)(wm * 64 + mi * 16 + (lane & 15)) * 80u + kcb;
                ldm_x4(a_hi[mi], uAh + off);
                ldm_x4(a_lo[mi], uAl + off);
            }
            #pragma unroll
            for (int g = 0; g < 2; g++) {
                uint32_t off = (uint32_t)(wn * 32 + g * 16 + (lane & 15)) * 80u + kcb;
                uint32_t th[4], tl[4];
                ldm_x4(th, uBh + off);
                ldm_x4(tl, uBl + off);
                b_hi[g*2+0][0] = th[0]; b_hi[g*2+0][1] = th[2];
                b_hi[g*2+1][0] = th[1]; b_hi[g*2+1][1] = th[3];
                b_lo[g*2+0][0] = tl[0]; b_lo[g*2+0][1] = tl[2];
                b_lo[g*2+1][0] = tl[1]; b_lo[g*2+1][1] = tl[3];
            }
            #pragma unroll
            for (int mi = 0; mi < 4; mi++)
                #pragma unroll
                for (int n = 0; n < 4; n++) {
                    mma_bf16(acc[mi][n], a_hi[mi], b_hi[n]);
                    mma_bf16(acc[mi][n], a_hi[mi], b_lo[n]);
                    mma_bf16(acc[mi][n], a_lo[mi], b_hi[n]);
                }
        }
    };

    const int nk = K / BK;
    load_stage(0, 0);
    for (int i = 0; i < nk; i++) {
        const int cur = i & 1;
        if (i + 1 < nk) {
            load_stage(cur ^ 1, (i + 1) * BK);
            asm volatile("cp.async.wait_group 1;" ::: "memory");
        } else {
            asm volatile("cp.async.wait_group 0;" ::: "memory");
        }
        __syncthreads();
        compute_stage(cur);
        __syncthreads();
    }

    // ---- epilogue ----
    const bool hb = (bias != nullptr);
    #pragma unroll
    for (int mi = 0; mi < 4; mi++) {
        #pragma unroll
        for (int n = 0; n < 4; n++) {
            int gc = col0 + wn * 32 + n * 8 + (lane & 3) * 2;
            float bx = 0.f, by = 0.f;
            if (hb) { bx = bias[gc]; by = bias[gc + 1]; }
            #pragma unroll
            for (int h = 0; h < 2; h++) {
                int gr = row0 + wm * 64 + mi * 16 + (lane >> 2) + h * 8;
                if (gr >= M) continue;
                float ox = acc[mi][n][h * 2 + 0] + bx;
                float oy = acc[mi][n][h * 2 + 1] + by;
                if (do_relu) { ox = fmaxf(ox, 0.f); oy = fmaxf(oy, 0.f); }
                size_t o = (size_t)gr * N + gc;
                if (Cf)
                    *reinterpret_cast<float2*>(&Cf[o]) = make_float2(ox, oy);
                if (Chi) {
                    *reinterpret_cast<uint32_t*>(&Chi[o]) = pack_hi(ox, oy);
                    *reinterpret_cast<uint32_t*>(&Clo[o]) = pack_lo(ox, oy);
                }
            }
        }
    }
}

// ---------------- im2col (emits bf16 hi/lo) ---------------------------------
__global__ void im2col_kernel(const float* __restrict__ x,
                              __nv_bfloat16* __restrict__ hi,
                              __nv_bfloat16* __restrict__ lo)
{
    int idx = blockIdx.x * blockDim.x + threadIdx.x;
    if (idx >= PROWS * EMB) return;
    int row = idx / EMB;
    int k   = idx % EMB;
    int b   = row / NP;
    int p   = row % NP;
    int py  = p / 14, px = p % 14;
    int c   = k / 256;
    int r2  = k % 256;
    int ph  = r2 / PATCH, pw = r2 % PATCH;
    float v = x[(((size_t)b * 3 + c) * IMG + (py * PATCH + ph)) * IMG
                + (px * PATCH + pw)];
    __nv_bfloat16 h = __float2bfloat16(v);
    hi[idx] = h;
    lo[idx] = __float2bfloat16(v - __bfloat162float(h));
}

__global__ void embed_kernel(const float* __restrict__ patch,
                             const float* __restrict__ cls_tok,
                             const float* __restrict__ pos,
                             float* __restrict__ h,
                             __nv_bfloat16* __restrict__ hhi,
                             __nv_bfloat16* __restrict__ hlo)
{
    int idx = blockIdx.x * blockDim.x + threadIdx.x;
    if (idx >= ROWS * EMB) return;
    int row = idx / EMB;
    int e   = idx % EMB;
    int b   = row / NTOK;
    int n   = row % NTOK;
    float base = (n == 0) ? cls_tok[e]
                          : patch[((size_t)b * NP + (n - 1)) * EMB + e];
    float v = base + pos[n * EMB + e];
    h[idx] = v;
    __nv_bfloat16 hh = __float2bfloat16(v);
    hhi[idx] = hh;
    hlo[idx] = __float2bfloat16(v - __bfloat162float(hh));
}

// ---------------- attention (reads fused qkv, stride 2304) ------------------
__global__ __launch_bounds__(256)
void attn_scores(const float* __restrict__ qkv, float* __restrict__ scores)
{
    const int bh = blockIdx.z;
    const int b  = bh / NHEAD;
    const int hh = bh % NHEAD;
    const int q0 = blockIdx.y * 32;
    const int k0 = blockIdx.x * 32;
    const float scale = 0.036084391824f;

    __shared__ __align__(16) float Qs[32][65];
    __shared__ __align__(16) float Ks[32][65];

    const int tid = threadIdx.x;
    const float* Qb = qkv + (size_t)b * NTOK * QS + hh * HD;
    const float* Kb = qkv + (size_t)b * NTOK * QS + 768 + hh * HD;

    #pragma unroll
    for (int l = 0; l < 2; l++) {
        int idx = tid + l * 256;
        int r   = idx >> 4;
        int c4  = (idx & 15) << 2;
        float4 vq = make_float4(0.f,0.f,0.f,0.f);
        float4 vk = make_float4(0.f,0.f,0.f,0.f);
        if (q0 + r < NTOK)
            vq = *reinterpret_cast<const float4*>(&Qb[(size_t)(q0 + r) * QS + c4]);
        if (k0 + r < NTOK)
            vk = *reinterpret_cast<const float4*>(&Kb[(size_t)(k0 + r) * QS + c4]);
        Qs[r][c4+0]=vq.x; Qs[r][c4+1]=vq.y; Qs[r][c4+2]=vq.z; Qs[r][c4+3]=vq.w;
        Ks[r][c4+0]=vk.x; Ks[r][c4+1]=vk.y; Ks[r][c4+2]=vk.z; Ks[r][c4+3]=vk.w;
    }
    __syncthreads();

    const int tx = tid & 15;
    const int ty = tid >> 4;
    float acc[2][2] = {{0.f,0.f},{0.f,0.f}};
    #pragma unroll
    for (int kk = 0; kk < HD; kk++) {
        float a0 = Qs[ty*2+0][kk], a1 = Qs[ty*2+1][kk];
        float b0 = Ks[tx*2+0][kk], b1 = Ks[tx*2+1][kk];
        acc[0][0] = fmaf(a0,b0,acc[0][0]);
        acc[0][1] = fmaf(a0,b1,acc[0][1]);
        acc[1][0] = fmaf(a1,b0,acc[1][0]);
        acc[1][1] = fmaf(a1,b1,acc[1][1]);
    }
    #pragma unroll
    for (int i = 0; i < 2; i++) {
        int qr = q0 + ty*2 + i;
        if (qr >= NTOK) continue;
        #pragma unroll
        for (int j = 0; j < 2; j++) {
            int kc = k0 + tx*2 + j;
            if (kc >= NTOK) continue;
            scores[((size_t)bh * NTOK + qr) * NTOK + kc] = acc[i][j] * scale;
        }
    }
}

__global__ __launch_bounds__(256)
void softmax_kernel(float* __restrict__ scores, int nrows)
{
    int row = blockIdx.x * 8 + (threadIdx.x >> 5);
    if (row >= nrows) return;
    int lane = threadIdx.x & 31;
    float* p = scores + (size_t)row * NTOK;

    float vals[7];
    float mx = -1e30f;
    #pragma unroll
    for (int i = 0; i < 7; i++) {
        int c = i * 32 + lane;
        vals[i] = (c < NTOK) ? p[c] : -1e30f;
        mx = fmaxf(mx, vals[i]);
    }
    #pragma unroll
    for (int o = 16; o; o >>= 1) mx = fmaxf(mx, __shfl_xor_sync(0xffffffffu, mx, o));

    float s = 0.f;
    #pragma unroll
    for (int i = 0; i < 7; i++) {
        vals[i] = expf(vals[i] - mx);
        s += vals[i];
    }
    #pragma unroll
    for (int o = 16; o; o >>= 1) s += __shfl_xor_sync(0xffffffffu, s, o);
    float inv = 1.f / s;
    #pragma unroll
    for (int i = 0; i < 7; i++) {
        int c = i * 32 + lane;
        if (c < NTOK) p[c] = vals[i] * inv;
    }
}

// out = attn @ V, emits bf16 hi/lo directly
__global__ __launch_bounds__(256)
void attn_av(const float* __restrict__ attn, const float* __restrict__ qkv,
             __nv_bfloat16* __restrict__ thi, __nv_bfloat16* __restrict__ tlo)
{
    const int bh = blockIdx.y;
    const int b  = bh / NHEAD;
    const int hh = bh % NHEAD;
    const int q0 = blockIdx.x * 32;

    __shared__ __align__(16) float As[32][33];
    __shared__ __align__(16) float Vs[32][64];

    const int tid = threadIdx.x;
    const int tx  = tid & 15;
    const int ty  = tid >> 4;
    const float* Arow = attn + (size_t)bh * NTOK * NTOK;
    const float* Vb   = qkv + (size_t)b * NTOK * QS + 1536 + hh * HD;

    float acc[2][4] = {};

    for (int kt = 0; kt < NTOK; kt += 32) {
        {
            int base = tid * 4;
            int r = base >> 5;
            int c = base & 31;
            #pragma unroll
            for (int u = 0; u < 4; u++) {
                int qr = q0 + r, kc = kt + c + u;
                As[r][c + u] = (qr < NTOK && kc < NTOK)
                               ? Arow[(size_t)qr * NTOK + kc] : 0.f;
            }
        }
        #pragma unroll
        for (int l = 0; l < 2; l++) {
            int idx = tid + l * 256;
            int r   = idx >> 4;
            int c4  = (idx & 15) << 2;
            float4 val = make_float4(0.f,0.f,0.f,0.f);
            if (kt + r < NTOK)
                val = *reinterpret_cast<const float4*>(&Vb[(size_t)(kt + r) * QS + c4]);
            *reinterpret_cast<float4*>(&Vs[r][c4]) = val;
        }
        __syncthreads();

        #pragma unroll
        for (int kk = 0; kk < 32; kk++) {
            float a0 = As[ty*2+0][kk];
            float a1 = As[ty*2+1][kk];
            float rb[4];
            *reinterpret_cast<float4*>(rb) =
                *reinterpret_cast<const float4*>(&Vs[kk][tx*4]);
            #pragma unroll
            for (int j = 0; j < 4; j++) {
                acc[0][j] = fmaf(a0, rb[j], acc[0][j]);
                acc[1][j] = fmaf(a1, rb[j], acc[1][j]);
            }
        }
        __syncthreads();
    }

    #pragma unroll
    for (int i = 0; i < 2; i++) {
        int qr = q0 + ty*2 + i;
        if (qr >= NTOK) continue;
        size_t o = ((size_t)b * NTOK + qr) * EMB + hh * HD + tx * 4;
        uint2 hp, lp;
        hp.x = pack_hi(acc[i][0], acc[i][1]);
        hp.y = pack_hi(acc[i][2], acc[i][3]);
        lp.x = pack_lo(acc[i][0], acc[i][1]);
        lp.y = pack_lo(acc[i][2], acc[i][3]);
        *reinterpret_cast<uint2*>(&thi[o]) = hp;
        *reinterpret_cast<uint2*>(&tlo[o]) = lp;
    }
}

// ---------------- fused residual add + LayerNorm (+ hi/lo emit) -------------
__global__ __launch_bounds__(256)
void add_ln(const float* __restrict__ a, const float* __restrict__ b,
            const float* __restrict__ g, const float* __restrict__ be,
            float* __restrict__ out,
            __nv_bfloat16* __restrict__ ohi, __nv_bfloat16* __restrict__ olo)
{
    const int r   = blockIdx.x;
    const int tid = threadIdx.x;
    float v[3];
    float s = 0.f, q = 0.f;
    #pragma unroll
    for (int t = 0; t < 3; t++) {
        int c = tid + t * 256;
        v[t] = a[(size_t)r * EMB + c] + b[(size_t)r * EMB + c];
        s += v[t];
        q += v[t] * v[t];
    }
    #pragma unroll
    for (int o = 16; o; o >>= 1) {
        s += __shfl_xor_sync(0xffffffffu, s, o);
        q += __shfl_xor_sync(0xffffffffu, q, o);
    }
    __shared__ float red[2][8];
    int w = tid >> 5, lane = tid & 31;
    if (lane == 0) { red[0][w] = s; red[1][w] = q; }
    __syncthreads();
    s = 0.f; q = 0.f;
    #pragma unroll
    for (int i = 0; i < 8; i++) { s += red[0][i]; q += red[1][i]; }
    float mean = s * (1.f / EMB);
    float var  = q * (1.f / EMB) - mean * mean;
    float rstd = rsqrtf(var + EPS);
    #pragma unroll
    for (int t = 0; t < 3; t++) {
        int c = tid + t * 256;
        float o = (v[t] - mean) * rstd * g[c] + be[c];
        size_t idx = (size_t)r * EMB + c;
        out[idx] = o;
        __nv_bfloat16 h = __float2bfloat16(o);
        ohi[idx] = h;
        olo[idx] = __float2bfloat16(o - __bfloat162float(h));
    }
}

__global__ __launch_bounds__(256)
void cls_ln(const float* __restrict__ h, const float* __restrict__ g,
            const float* __restrict__ be, float* __restrict__ out)
{
    const int b   = blockIdx.x;
    const int tid = threadIdx.x;
    const float* row = h + (size_t)b * NTOK * EMB;
    float v[3];
    float s = 0.f, q = 0.f;
    #pragma unroll
    for (int t = 0; t < 3; t++) {
        int c = tid + t * 256;
        v[t] = row[c];
        s += v[t];
        q += v[t] * v[t];
    }
    #pragma unroll
    for (int o = 16; o; o >>= 1) {
        s += __shfl_xor_sync(0xffffffffu, s, o);
        q += __shfl_xor_sync(0xffffffffu, q, o);
    }
    __shared__ float red[2][8];
    int w = tid >> 5, lane = tid & 31;
    if (lane == 0) { red[0][w] = s; red[1][w] = q; }
    __syncthreads();
    s = 0.f; q = 0.f;
    #pragma unroll
    for (int i = 0; i < 8; i++) { s += red[0][i]; q += red[1][i]; }
    float mean = s * (1.f / EMB);
    float var  = q * (1.f / EMB) - mean * mean;
    float rstd = rsqrtf(var + EPS);
    #pragma unroll
    for (int t = 0; t < 3; t++) {
        int c = tid + t * 256;
        out[(size_t)b * EMB + c] = (v[t] - mean) * rstd * g[c] + be[c];
    }
}

// ---------------- classifier head -------------------------------------------
__global__ __launch_bounds__(256)
void head_gemm(const float* __restrict__ cls, const float* __restrict__ W,
               const float* __restrict__ bias, float* __restrict__ out)
{
    int idx = blockIdx.x * blockDim.x + threadIdx.x;
    if (idx >= BATCH * NCLS) return;
    int b = idx / NCLS;
    int n = idx % NCLS;
    float s = bias[n];
    const float* c = cls + (size_t)b * EMB;
    for (int k = 0; k < EMB; k++)
        s = fmaf(c[k], W[(size_t)k * NCLS + n], s);
    out[idx] = s;
}

// ---------------- driver -----------------------------------------------------
extern "C" void kernel_launch(void* const* d_in, const int* in_sizes, int n_in,
                              void* d_out, int out_size)
{
    const float* x        = (const float*)d_in[0];
    const float* conv_w   = (const float*)d_in[1];
    const float* conv_b   = (const float*)d_in[2];
    const float* cls_tok  = (const float*)d_in[3];
    const float* pos_emb  = (const float*)d_in[4];
    const float* Wq       = (const float*)d_in[5];
    const float* Wk       = (const float*)d_in[6];
    const float* Wv       = (const float*)d_in[7];
    const float* Wo       = (const float*)d_in[8];
    const float* bo       = (const float*)d_in[9];
    const float* ln1_g    = (const float*)d_in[10];
    const float* ln1_b    = (const float*)d_in[11];
    const float* W1       = (const float*)d_in[12];
    const float* b1       = (const float*)d_in[13];
    const float* W2       = (const float*)d_in[14];
    const float* b2       = (const float*)d_in[15];
    const float* ln2_g    = (const float*)d_in[16];
    const float* ln2_b    = (const float*)d_in[17];
    const float* head_g   = (const float*)d_in[18];
    const float* head_b   = (const float*)d_in[19];
    const float* head_W   = (const float*)d_in[20];
    const float* head_bias= (const float*)d_in[21];
    float* out = (float*)d_out;

    float *ph, *px, *pt, *pqkv, *psc, *pcls;
    __nv_bfloat16 *phhi, *phlo, *pxhi, *pxlo, *pthi, *ptlo, *pfhi, *pflo;
    __nv_bfloat16 *pimhi, *pimlo, *pwhi, *pwlo, *pcwhi, *pcwlo;
    cudaGetSymbolAddress((void**)&ph,    g_h);
    cudaGetSymbolAddress((void**)&px,    g_x);
    cudaGetSymbolAddress((void**)&pt,    g_t);
    cudaGetSymbolAddress((void**)&pqkv,  g_qkv);
    cudaGetSymbolAddress((void**)&psc,   g_sc);
    cudaGetSymbolAddress((void**)&pcls,  g_cls);
    cudaGetSymbolAddress((void**)&phhi,  g_hhi);
    cudaGetSymbolAddress((void**)&phlo,  g_hlo);
    cudaGetSymbolAddress((void**)&pxhi,  g_xhi);
    cudaGetSymbolAddress((void**)&pxlo,  g_xlo);
    cudaGetSymbolAddress((void**)&pthi,  g_thi);
    cudaGetSymbolAddress((void**)&ptlo,  g_tlo);
    cudaGetSymbolAddress((void**)&pfhi,  g_fhi);
    cudaGetSymbolAddress((void**)&pflo,  g_flo);
    cudaGetSymbolAddress((void**)&pimhi, g_imhi);
    cudaGetSymbolAddress((void**)&pimlo, g_imlo);
    cudaGetSymbolAddress((void**)&pwhi,  g_whi);
    cudaGetSymbolAddress((void**)&pwlo,  g_wlo);
    cudaGetSymbolAddress((void**)&pcwhi, g_cwhi);
    cudaGetSymbolAddress((void**)&pcwlo, g_cwlo);

    cudaFuncSetAttribute(gemm_hmma, cudaFuncAttributeMaxDynamicSharedMemorySize,
                         GEMM_SMEM);

    // ---- weight prep: batched transpose + split (6 launches) ----
    {
        dim3 blk(32, 8);
        dim3 gEE(EMB/32, EMB/32, DEPTH);
        transpose_split_batch<<<gEE, blk>>>(Wq, pwhi + OFF_Q, pwlo + OFF_Q,
                                            EMB, EMB, (size_t)EMB*EMB, LSTRIDE);
        transpose_split_batch<<<gEE, blk>>>(Wk, pwhi + OFF_K, pwlo + OFF_K,
                                            EMB, EMB, (size_t)EMB*EMB, LSTRIDE);
        transpose_split_batch<<<gEE, blk>>>(Wv, pwhi + OFF_V, pwlo + OFF_V,
                                            EMB, EMB, (size_t)EMB*EMB, LSTRIDE);
        transpose_split_batch<<<gEE, blk>>>(Wo, pwhi + OFF_O, pwlo + OFF_O,
                                            EMB, EMB, (size_t)EMB*EMB, LSTRIDE);
        dim3 g1(FF/32, EMB/32, DEPTH);
        transpose_split_batch<<<g1, blk>>>(W1, pwhi + OFF_W1, pwlo + OFF_W1,
                                           EMB, FF, (size_t)EMB*FF, LSTRIDE);
        dim3 g2(EMB/32, FF/32, DEPTH);
        transpose_split_batch<<<g2, blk>>>(W2, pwhi + OFF_W2, pwlo + OFF_W2,
                                           FF, EMB, (size_t)FF*EMB, LSTRIDE);
        split_only<<<(EMB*EMB + 255)/256, 256>>>(conv_w, pcwhi, pcwlo, EMB*EMB);
    }

    // ---- patch embedding ----
    im2col_kernel<<<(PROWS*EMB + 255)/256, 256>>>(x, pimhi, pimlo);
    gemm_hmma<<<dim3(EMB/BN, PROWS/BM), 256, GEMM_SMEM>>>(
        pimhi, pimlo, pcwhi, pcwlo, conv_b, pt, nullptr, nullptr,
        PROWS, EMB, EMB, 0);
    embed_kernel<<<(ROWS*EMB + 255)/256, 256>>>(pt, cls_tok, pos_emb,
                                                ph, phhi, phlo);

    const int mtiles = (ROWS + BM - 1) / BM;   // 50
    const dim3 gQKV(QS/BN, mtiles);            // 18 x 50
    const dim3 gE(EMB/BN,  mtiles);            // 6 x 50
    const dim3 gF1(FF/BN,  mtiles);            // 24 x 50
    const dim3 gS(7, 7, BATCH*NHEAD);
    const dim3 gA(7, BATCH*NHEAD);
    const int  smrows = BATCH*NHEAD*NTOK;

    for (int l = 0; l < DEPTH; l++) {
        size_t base = (size_t)l * LSTRIDE;
        const __nv_bfloat16* qkvh = pwhi + base + OFF_Q;  // [2304, 768]
        const __nv_bfloat16* qkvl = pwlo + base + OFF_Q;
        const __nv_bfloat16* oh = pwhi + base + OFF_O;
        const __nv_bfloat16* ol = pwlo + base + OFF_O;
        const __nv_bfloat16* w1h= pwhi + base + OFF_W1;
        const __nv_bfloat16* w1l= pwlo + base + OFF_W1;
        const __nv_bfloat16* w2h= pwhi + base + OFF_W2;
        const __nv_bfloat16* w2l= pwlo + base + OFF_W2;
        const float* bol= bo + (size_t)l*EMB;
        const float* g1 = ln1_g + (size_t)l*EMB;
        const float* be1= ln1_b + (size_t)l*EMB;
        const float* bb1= b1 + (size_t)l*FF;
        const float* bb2= b2 + (size_t)l*EMB;
        const float* g2 = ln2_g + (size_t)l*EMB;
        const float* be2= ln2_b + (size_t)l*EMB;

        // fused QKV
        gemm_hmma<<<gQKV, 256, GEMM_SMEM>>>(phhi, phlo, qkvh, qkvl, nullptr,
                                            pqkv, nullptr, nullptr,
                                            ROWS, QS, EMB, 0);

        attn_scores<<<gS, 256>>>(pqkv, psc);
        softmax_kernel<<<(smrows + 7)/8, 256>>>(psc, smrows);
        attn_av<<<gA, 256>>>(psc, pqkv, pthi, ptlo);

        gemm_hmma<<<gE, 256, GEMM_SMEM>>>(pthi, ptlo, oh, ol, bol,
                                          pt, nullptr, nullptr,
                                          ROWS, EMB, EMB, 0);
        add_ln<<<ROWS, 256>>>(pt, ph, g1, be1, px, pxhi, pxlo);

        gemm_hmma<<<gF1, 256, GEMM_SMEM>>>(pxhi, pxlo, w1h, w1l, bb1,
                                           nullptr, pfhi, pflo,
                                           ROWS, FF, EMB, 1);
        gemm_hmma<<<gE, 256, GEMM_SMEM>>>(pfhi, pflo, w2h, w2l, bb2,
                                          pt, nullptr, nullptr,
                                          ROWS, EMB, FF, 0);
        add_ln<<<ROWS, 256>>>(pt, px, g2, be2, ph, phhi, phlo);
    }

    cls_ln<<<BATCH, 256>>>(ph, head_g, head_b, pcls);
    head_gemm<<<(BATCH*NCLS + 255)/256, 256>>>(pcls, head_W, head_bias, out);
}

// round 6
// speedup vs baseline: 2.3452x; 1.1724x over previous
#include <cuda_runtime.h>
#include <cuda_fp16.h>
#include <cstdint>
#include <cstddef>

// ---------------- Problem constants ----------------
#define IMG   224
#define PATCH 16
#define EMB   768
#define DEPTH 12
#define NHEAD 12
#define HD    64
#define FF    3072
#define NCLS  1000
#define BATCH 32
#define NP    196
#define NTOK  197
#define ROWS  (BATCH * NTOK) // 6304
#define PROWS (BATCH * NP)   // 6272
#define EPS   1e-5f
#define QS    2304           // fused qkv row stride

// weight layout (per layer, element offsets). Q,K,V contiguous -> fused QKV.
#define OFF_Q   0
#define OFF_K   589824
#define OFF_V   1179648
#define OFF_O   1769472
#define OFF_W1  2359296
#define OFF_W2  4718592
#define LSTRIDE 7077888
#define WTOTAL  (LSTRIDE * DEPTH)

// ---------------- Scratch ----------------
__device__ float g_h  [ROWS * EMB];     // layer activation fp32
__device__ float g_x  [ROWS * EMB];     // post-LN1 fp32
__device__ float g_t  [ROWS * EMB];     // O-proj / conv out fp32
__device__ float g_qkv[ROWS * QS];      // fused qkv fp32
__device__ float g_cls[BATCH * EMB];
__device__ __half g_hhi[ROWS * EMB],  g_hlo[ROWS * EMB];
__device__ __half g_xhi[ROWS * EMB],  g_xlo[ROWS * EMB];
__device__ __half g_thi[ROWS * EMB],  g_tlo[ROWS * EMB];
__device__ __half g_fhi[ROWS * FF],   g_flo[ROWS * FF];
__device__ __half g_imhi[PROWS * EMB], g_imlo[PROWS * EMB];
__device__ __half g_w  [WTOTAL];        // weights single fp16, [N,K]
__device__ __half g_cw [EMB * EMB];

// ---------------- helpers ----------------
__device__ __forceinline__ uint32_t smem_u32(const void* p) {
    uint32_t a;
    asm("{ .reg .u64 t; cvta.to.shared.u64 t, %1; cvt.u32.u64 %0, t; }"
        : "=r"(a) : "l"(p));
    return a;
}
__device__ __forceinline__ void ldm_x4(uint32_t (&r)[4], uint32_t addr) {
    asm volatile("ldmatrix.sync.aligned.m8n8.x4.shared.b16 {%0,%1,%2,%3}, [%4];"
                 : "=r"(r[0]), "=r"(r[1]), "=r"(r[2]), "=r"(r[3]) : "r"(addr));
}
__device__ __forceinline__ void mma_f16(float (&d)[4], const uint32_t (&a)[4],
                                        const uint32_t (&b)[2]) {
    asm volatile("mma.sync.aligned.m16n8k16.row.col.f32.f16.f16.f32 "
                 "{%0,%1,%2,%3}, {%4,%5,%6,%7}, {%8,%9}, {%0,%1,%2,%3};"
                 : "+f"(d[0]), "+f"(d[1]), "+f"(d[2]), "+f"(d[3])
                 : "r"(a[0]), "r"(a[1]), "r"(a[2]), "r"(a[3]),
                   "r"(b[0]), "r"(b[1]));
}
__device__ __forceinline__ uint32_t pack_hi16(float x, float y) {
    __half2 h = __floats2half2_rn(x, y);
    return *reinterpret_cast<uint32_t*>(&h);
}
__device__ __forceinline__ uint32_t pack_lo16(float x, float y) {
    float rx = x - __half2float(__float2half_rn(x));
    float ry = y - __half2float(__float2half_rn(y));
    __half2 h = __floats2half2_rn(rx, ry);
    return *reinterpret_cast<uint32_t*>(&h);
}

// ---------------- weight prep: transpose [K,N] -> [N,K], fp16 ---------------
__global__ void transpose_half_batch(const float* __restrict__ W,
                                     __half* __restrict__ out,
                                     int K, int N,
                                     size_t w_lstride, size_t o_lstride)
{
    __shared__ float t[32][33];
    const int layer = blockIdx.z;
    W   += (size_t)layer * w_lstride;
    out += (size_t)layer * o_lstride;
    int nb = blockIdx.x * 32, kb = blockIdx.y * 32;
    int tx = threadIdx.x, ty = threadIdx.y;
    #pragma unroll
    for (int j = ty; j < 32; j += 8)
        t[j][tx] = W[(size_t)(kb + j) * N + nb + tx];
    __syncthreads();
    #pragma unroll
    for (int j = ty; j < 32; j += 8)
        out[(size_t)(nb + j) * K + kb + tx] = __float2half_rn(t[tx][j]);
}

__global__ void tohalf_only(const float* __restrict__ W,
                            __half* __restrict__ out, int n)
{
    int i = blockIdx.x * blockDim.x + threadIdx.x;
    if (i < n) out[i] = __float2half_rn(W[i]);
}

// ---------------- pipelined HMMA GEMM ----------------------------------------
// C[M,N] = (Ahi+Alo)[M,K] @ B[N,K]^T   (fp16 2-pass, fp32 accum)
#define BM 128
#define BN 128
#define BK 32
#define ARR_B 10240                 // 128 * 40 * 2B
#define STAGE_B (3 * ARR_B)         // Ahi, Alo, B
#define GEMM_SMEM (2 * STAGE_B)     // 61440 B

__global__ __launch_bounds__(256)
void gemm_hmma(const __half* __restrict__ Ahi,
               const __half* __restrict__ Alo,
               const __half* __restrict__ B,
               const float* __restrict__ bias,
               float* __restrict__ Cf,
               __half* __restrict__ Chi,
               __half* __restrict__ Clo,
               int M, int N, int K, int do_relu)
{
    extern __shared__ __align__(16) unsigned char dsm[];
    const uint32_t smb = smem_u32(dsm);
    const int tid  = threadIdx.x;
    const int lane = tid & 31;
    const int wid  = tid >> 5;
    const int wm   = wid & 1;
    const int wn   = wid >> 1;
    const int row0 = blockIdx.y * BM;
    const int col0 = blockIdx.x * BN;

    float acc[4][4][4] = {};
    const __half* srcs[3] = {Ahi, Alo, B};

    auto load_stage = [&](int s, int kt) {
        #pragma unroll
        for (int l = 0; l < 6; l++) {
            int idx = tid + l * 256;     // 0..1535
            int arr = idx >> 9;          // 0 Ahi, 1 Alo, 2 B
            int w   = idx & 511;
            int r   = w >> 2;
            int q   = w & 3;
            int row = (arr < 2 ? row0 : col0) + r;
            const __half* src = srcs[arr] + (size_t)row * K + kt + q * 8;
            int bytes = (arr < 2 && row >= M) ? 0 : 16;
            uint32_t dst = smb + (uint32_t)s * STAGE_B + (uint32_t)arr * ARR_B
                         + (uint32_t)r * 80u + (uint32_t)q * 16u;
            asm volatile("cp.async.cg.shared.global [%0], [%1], 16, %2;"
                         :: "r"(dst), "l"(src), "r"(bytes) : "memory");
        }
        asm volatile("cp.async.commit_group;" ::: "memory");
    };

    auto compute_stage = [&](int s) {
        const uint32_t uAh = smb + (uint32_t)s * STAGE_B;
        const uint32_t uAl = uAh + ARR_B;
        const uint32_t uB  = uAh + 2 * ARR_B;
        #pragma unroll
        for (int kk = 0; kk < 2; kk++) {
            const uint32_t kcb = (kk * 16 + ((lane >> 4) << 3)) * 2;
            uint32_t a_hi[4][4], a_lo[4][4];
            uint32_t bf[4][2];
            #pragma unroll
            for (int mi = 0; mi < 4; mi++) {
                uint32_t off = (uint32_t)(wm * 64 + mi * 16 + (lane & 15)) * 80u + kcb;
                ldm_x4(a_hi[mi], uAh + off);
                ldm_x4(a_lo[mi], uAl + off);
            }
            #pragma unroll
            for (int g = 0; g < 2; g++) {
                uint32_t off = (uint32_t)(wn * 32 + g * 16 + (lane & 15)) * 80u + kcb;
                uint32_t tb[4];
                ldm_x4(tb, uB + off);
                bf[g*2+0][0] = tb[0]; bf[g*2+0][1] = tb[2];
                bf[g*2+1][0] = tb[1]; bf[g*2+1][1] = tb[3];
            }
            #pragma unroll
            for (int mi = 0; mi < 4; mi++)
                #pragma unroll
                for (int n = 0; n < 4; n++) {
                    mma_f16(acc[mi][n], a_hi[mi], bf[n]);
                    mma_f16(acc[mi][n], a_lo[mi], bf[n]);
                }
        }
    };

    const int nk = K / BK;
    load_stage(0, 0);
    for (int i = 0; i < nk; i++) {
        const int cur = i & 1;
        if (i + 1 < nk) {
            load_stage(cur ^ 1, (i + 1) * BK);
            asm volatile("cp.async.wait_group 1;" ::: "memory");
        } else {
            asm volatile("cp.async.wait_group 0;" ::: "memory");
        }
        __syncthreads();
        compute_stage(cur);
        __syncthreads();
    }

    // ---- epilogue ----
    const bool hb = (bias != nullptr);
    #pragma unroll
    for (int mi = 0; mi < 4; mi++) {
        #pragma unroll
        for (int n = 0; n < 4; n++) {
            int gc = col0 + wn * 32 + n * 8 + (lane & 3) * 2;
            float bx = 0.f, by = 0.f;
            if (hb) { bx = bias[gc]; by = bias[gc + 1]; }
            #pragma unroll
            for (int h = 0; h < 2; h++) {
                int gr = row0 + wm * 64 + mi * 16 + (lane >> 2) + h * 8;
                if (gr >= M) continue;
                float ox = acc[mi][n][h * 2 + 0] + bx;
                float oy = acc[mi][n][h * 2 + 1] + by;
                if (do_relu) { ox = fmaxf(ox, 0.f); oy = fmaxf(oy, 0.f); }
                size_t o = (size_t)gr * N + gc;
                if (Cf)
                    *reinterpret_cast<float2*>(&Cf[o]) = make_float2(ox, oy);
                if (Chi) {
                    *reinterpret_cast<uint32_t*>(&Chi[o]) = pack_hi16(ox, oy);
                    *reinterpret_cast<uint32_t*>(&Clo[o]) = pack_lo16(ox, oy);
                }
            }
        }
    }
}

// ---------------- im2col (emits fp16 hi/lo) ---------------------------------
__global__ void im2col_kernel(const float* __restrict__ x,
                              __half* __restrict__ hi,
                              __half* __restrict__ lo)
{
    int idx = blockIdx.x * blockDim.x + threadIdx.x;
    if (idx >= PROWS * EMB) return;
    int row = idx / EMB;
    int k   = idx % EMB;
    int b   = row / NP;
    int p   = row % NP;
    int py  = p / 14, px = p % 14;
    int c   = k / 256;
    int r2  = k % 256;
    int ph  = r2 / PATCH, pw = r2 % PATCH;
    float v = x[(((size_t)b * 3 + c) * IMG + (py * PATCH + ph)) * IMG
                + (px * PATCH + pw)];
    __half h = __float2half_rn(v);
    hi[idx] = h;
    lo[idx] = __float2half_rn(v - __half2float(h));
}

__global__ void embed_kernel(const float* __restrict__ patch,
                             const float* __restrict__ cls_tok,
                             const float* __restrict__ pos,
                             float* __restrict__ h,
                             __half* __restrict__ hhi,
                             __half* __restrict__ hlo)
{
    int idx = blockIdx.x * blockDim.x + threadIdx.x;
    if (idx >= ROWS * EMB) return;
    int row = idx / EMB;
    int e   = idx % EMB;
    int b   = row / NTOK;
    int n   = row % NTOK;
    float base = (n == 0) ? cls_tok[e]
                          : patch[((size_t)b * NP + (n - 1)) * EMB + e];
    float v = base + pos[n * EMB + e];
    h[idx] = v;
    __half hh = __float2half_rn(v);
    hhi[idx] = hh;
    hlo[idx] = __float2half_rn(v - __half2float(hh));
}

// ---------------- fused attention: scores + softmax + AV ---------------------
// grid(7 q-blocks, B*H), 256 threads. scores kept in smem.
#define SCP 224   // score row stride; cols 197..223 zero-padded for AV tail tile

__global__ __launch_bounds__(256)
void attn_fused(const float* __restrict__ qkv,
                __half* __restrict__ thi, __half* __restrict__ tlo)
{
    __shared__ __align__(16) float Qs[32][68];
    __shared__ __align__(16) float KV[32][68];
    __shared__ float sc[32][SCP];

    const int bh = blockIdx.y;
    const int b  = bh / NHEAD;
    const int hh = bh % NHEAD;
    const int q0 = blockIdx.x * 32;
    const float scale = 0.036084391824f;   // 1/sqrt(768)

    const int tid  = threadIdx.x;
    const int lane = tid & 31;
    const int wrp  = tid >> 5;
    const int tx   = tid & 15;
    const int ty   = tid >> 4;

    const float* Qb = qkv + (size_t)b * NTOK * QS + hh * HD;
    const float* Kb = Qb + 768;
    const float* Vb = Qb + 1536;

    // load Q tile
    #pragma unroll
    for (int l = 0; l < 2; l++) {
        int idx = tid + l * 256;
        int r   = idx >> 4;
        int c4  = (idx & 15) << 2;
        float4 vq = make_float4(0.f, 0.f, 0.f, 0.f);
        if (q0 + r < NTOK)
            vq = *reinterpret_cast<const float4*>(&Qb[(size_t)(q0 + r) * QS + c4]);
        Qs[r][c4+0]=vq.x; Qs[r][c4+1]=vq.y; Qs[r][c4+2]=vq.z; Qs[r][c4+3]=vq.w;
    }
    // zero the tail columns of sc (cols 192..223): AV tail tile multiplies by 0
    for (int i = tid; i < 32 * 32; i += 256)
        sc[i >> 5][192 + (i & 31)] = 0.f;
    __syncthreads();

    // ---- phase 1: scores ----
    for (int kt = 0; kt < NTOK; kt += 32) {
        #pragma unroll
        for (int l = 0; l < 2; l++) {
            int idx = tid + l * 256;
            int r   = idx >> 4;
            int c4  = (idx & 15) << 2;
            float4 vk = make_float4(0.f, 0.f, 0.f, 0.f);
            if (kt + r < NTOK)
                vk = *reinterpret_cast<const float4*>(&Kb[(size_t)(kt + r) * QS + c4]);
            KV[r][c4+0]=vk.x; KV[r][c4+1]=vk.y; KV[r][c4+2]=vk.z; KV[r][c4+3]=vk.w;
        }
        __syncthreads();

        float acc[2][2] = {{0.f,0.f},{0.f,0.f}};
        #pragma unroll
        for (int kk = 0; kk < HD; kk++) {
            float a0 = Qs[ty*2+0][kk], a1 = Qs[ty*2+1][kk];
            float b0 = KV[tx*2+0][kk], b1 = KV[tx*2+1][kk];
            acc[0][0] = fmaf(a0,b0,acc[0][0]);
            acc[0][1] = fmaf(a0,b1,acc[0][1]);
            acc[1][0] = fmaf(a1,b0,acc[1][0]);
            acc[1][1] = fmaf(a1,b1,acc[1][1]);
        }
        #pragma unroll
        for (int i = 0; i < 2; i++)
            #pragma unroll
            for (int j = 0; j < 2; j++) {
                int kc = kt + tx*2 + j;
                if (kc < NTOK) sc[ty*2+i][kc] = acc[i][j] * scale;
            }
        __syncthreads();
    }

    // ---- phase 2: softmax (warp w: rows w, w+8, w+16, w+24) ----
    #pragma unroll
    for (int rr = 0; rr < 4; rr++) {
        int row = wrp + rr * 8;
        float vals[7];
        float mx = -1e30f;
        #pragma unroll
        for (int i = 0; i < 7; i++) {
            int c = i * 32 + lane;
            vals[i] = (c < NTOK) ? sc[row][c] : -1e30f;
            mx = fmaxf(mx, vals[i]);
        }
        #pragma unroll
        for (int o = 16; o; o >>= 1) mx = fmaxf(mx, __shfl_xor_sync(0xffffffffu, mx, o));
        float s = 0.f;
        #pragma unroll
        for (int i = 0; i < 7; i++) { vals[i] = expf(vals[i] - mx); s += vals[i]; }
        #pragma unroll
        for (int o = 16; o; o >>= 1) s += __shfl_xor_sync(0xffffffffu, s, o);
        float inv = 1.f / s;
        #pragma unroll
        for (int i = 0; i < 7; i++) {
            int c = i * 32 + lane;
            if (c < NTOK) sc[row][c] = vals[i] * inv;
        }
    }
    __syncthreads();

    // ---- phase 3: out = attn @ V ----
    float acc[2][4] = {};
    for (int kt = 0; kt < NTOK; kt += 32) {
        #pragma unroll
        for (int l = 0; l < 2; l++) {
            int idx = tid + l * 256;
            int r   = idx >> 4;
            int c4  = (idx & 15) << 2;
            float4 vv = make_float4(0.f, 0.f, 0.f, 0.f);
            if (kt + r < NTOK)
                vv = *reinterpret_cast<const float4*>(&Vb[(size_t)(kt + r) * QS + c4]);
            KV[r][c4+0]=vv.x; KV[r][c4+1]=vv.y; KV[r][c4+2]=vv.z; KV[r][c4+3]=vv.w;
        }
        __syncthreads();

        #pragma unroll
        for (int kk = 0; kk < 32; kk++) {
            float a0 = sc[ty*2+0][kt+kk];
            float a1 = sc[ty*2+1][kt+kk];
            float rb[4];
            *reinterpret_cast<float4*>(rb) =
                *reinterpret_cast<const float4*>(&KV[kk][tx*4]);
            #pragma unroll
            for (int j = 0; j < 4; j++) {
                acc[0][j] = fmaf(a0, rb[j], acc[0][j]);
                acc[1][j] = fmaf(a1, rb[j], acc[1][j]);
            }
        }
        __syncthreads();
    }

    #pragma unroll
    for (int i = 0; i < 2; i++) {
        int qr = q0 + ty*2 + i;
        if (qr >= NTOK) continue;
        size_t o = ((size_t)b * NTOK + qr) * EMB + hh * HD + tx * 4;
        uint2 hp, lp;
        hp.x = pack_hi16(acc[i][0], acc[i][1]);
        hp.y = pack_hi16(acc[i][2], acc[i][3]);
        lp.x = pack_lo16(acc[i][0], acc[i][1]);
        lp.y = pack_lo16(acc[i][2], acc[i][3]);
        *reinterpret_cast<uint2*>(&thi[o]) = hp;
        *reinterpret_cast<uint2*>(&tlo[o]) = lp;
    }
}

// ---------------- fused residual add + LayerNorm (+ fp16 hi/lo emit) --------
__global__ __launch_bounds__(256)
void add_ln(const float* __restrict__ a, const float* __restrict__ b,
            const float* __restrict__ g, const float* __restrict__ be,
            float* __restrict__ out,
            __half* __restrict__ ohi, __half* __restrict__ olo)
{
    const int r   = blockIdx.x;
    const int tid = threadIdx.x;
    float v[3];
    float s = 0.f, q = 0.f;
    #pragma unroll
    for (int t = 0; t < 3; t++) {
        int c = tid + t * 256;
        v[t] = a[(size_t)r * EMB + c] + b[(size_t)r * EMB + c];
        s += v[t];
        q += v[t] * v[t];
    }
    #pragma unroll
    for (int o = 16; o; o >>= 1) {
        s += __shfl_xor_sync(0xffffffffu, s, o);
        q += __shfl_xor_sync(0xffffffffu, q, o);
    }
    __shared__ float red[2][8];
    int w = tid >> 5, lane = tid & 31;
    if (lane == 0) { red[0][w] = s; red[1][w] = q; }
    __syncthreads();
    s = 0.f; q = 0.f;
    #pragma unroll
    for (int i = 0; i < 8; i++) { s += red[0][i]; q += red[1][i]; }
    float mean = s * (1.f / EMB);
    float var  = q * (1.f / EMB) - mean * mean;
    float rstd = rsqrtf(var + EPS);
    #pragma unroll
    for (int t = 0; t < 3; t++) {
        int c = tid + t * 256;
        float o = (v[t] - mean) * rstd * g[c] + be[c];
        size_t idx = (size_t)r * EMB + c;
        out[idx] = o;
        __half h = __float2half_rn(o);
        ohi[idx] = h;
        olo[idx] = __float2half_rn(o - __half2float(h));
    }
}

__global__ __launch_bounds__(256)
void cls_ln(const float* __restrict__ h, const float* __restrict__ g,
            const float* __restrict__ be, float* __restrict__ out)
{
    const int b   = blockIdx.x;
    const int tid = threadIdx.x;
    const float* row = h + (size_t)b * NTOK * EMB;
    float v[3];
    float s = 0.f, q = 0.f;
    #pragma unroll
    for (int t = 0; t < 3; t++) {
        int c = tid + t * 256;
        v[t] = row[c];
        s += v[t];
        q += v[t] * v[t];
    }
    #pragma unroll
    for (int o = 16; o; o >>= 1) {
        s += __shfl_xor_sync(0xffffffffu, s, o);
        q += __shfl_xor_sync(0xffffffffu, q, o);
    }
    __shared__ float red[2][8];
    int w = tid >> 5, lane = tid & 31;
    if (lane == 0) { red[0][w] = s; red[1][w] = q; }
    __syncthreads();
    s = 0.f; q = 0.f;
    #pragma unroll
    for (int i = 0; i < 8; i++) { s += red[0][i]; q += red[1][i]; }
    float mean = s * (1.f / EMB);
    float var  = q * (1.f / EMB) - mean * mean;
    float rstd = rsqrtf(var + EPS);
    #pragma unroll
    for (int t = 0; t < 3; t++) {
        int c = tid + t * 256;
        out[(size_t)b * EMB + c] = (v[t] - mean) * rstd * g[c] + be[c];
    }
}

// ---------------- classifier head -------------------------------------------
__global__ __launch_bounds__(256)
void head_gemm(const float* __restrict__ cls, const float* __restrict__ W,
               const float* __restrict__ bias, float* __restrict__ out)
{
    int idx = blockIdx.x * blockDim.x + threadIdx.x;
    if (idx >= BATCH * NCLS) return;
    int b = idx / NCLS;
    int n = idx % NCLS;
    float s = bias[n];
    const float* c = cls + (size_t)b * EMB;
    for (int k = 0; k < EMB; k++)
        s = fmaf(c[k], W[(size_t)k * NCLS + n], s);
    out[idx] = s;
}

// ---------------- driver -----------------------------------------------------
extern "C" void kernel_launch(void* const* d_in, const int* in_sizes, int n_in,
                              void* d_out, int out_size)
{
    const float* x        = (const float*)d_in[0];
    const float* conv_w   = (const float*)d_in[1];
    const float* conv_b   = (const float*)d_in[2];
    const float* cls_tok  = (const float*)d_in[3];
    const float* pos_emb  = (const float*)d_in[4];
    const float* Wq       = (const float*)d_in[5];
    const float* Wk       = (const float*)d_in[6];
    const float* Wv       = (const float*)d_in[7];
    const float* Wo       = (const float*)d_in[8];
    const float* bo       = (const float*)d_in[9];
    const float* ln1_g    = (const float*)d_in[10];
    const float* ln1_b    = (const float*)d_in[11];
    const float* W1       = (const float*)d_in[12];
    const float* b1       = (const float*)d_in[13];
    const float* W2       = (const float*)d_in[14];
    const float* b2       = (const float*)d_in[15];
    const float* ln2_g    = (const float*)d_in[16];
    const float* ln2_b    = (const float*)d_in[17];
    const float* head_g   = (const float*)d_in[18];
    const float* head_b   = (const float*)d_in[19];
    const float* head_W   = (const float*)d_in[20];
    const float* head_bias= (const float*)d_in[21];
    float* out = (float*)d_out;

    float *ph, *px, *pt, *pqkv, *pcls;
    __half *phhi, *phlo, *pxhi, *pxlo, *pthi, *ptlo, *pfhi, *pflo;
    __half *pimhi, *pimlo, *pw, *pcw;
    cudaGetSymbolAddress((void**)&ph,    g_h);
    cudaGetSymbolAddress((void**)&px,    g_x);
    cudaGetSymbolAddress((void**)&pt,    g_t);
    cudaGetSymbolAddress((void**)&pqkv,  g_qkv);
    cudaGetSymbolAddress((void**)&pcls,  g_cls);
    cudaGetSymbolAddress((void**)&phhi,  g_hhi);
    cudaGetSymbolAddress((void**)&phlo,  g_hlo);
    cudaGetSymbolAddress((void**)&pxhi,  g_xhi);
    cudaGetSymbolAddress((void**)&pxlo,  g_xlo);
    cudaGetSymbolAddress((void**)&pthi,  g_thi);
    cudaGetSymbolAddress((void**)&ptlo,  g_tlo);
    cudaGetSymbolAddress((void**)&pfhi,  g_fhi);
    cudaGetSymbolAddress((void**)&pflo,  g_flo);
    cudaGetSymbolAddress((void**)&pimhi, g_imhi);
    cudaGetSymbolAddress((void**)&pimlo, g_imlo);
    cudaGetSymbolAddress((void**)&pw,    g_w);
    cudaGetSymbolAddress((void**)&pcw,   g_cw);

    cudaFuncSetAttribute(gemm_hmma, cudaFuncAttributeMaxDynamicSharedMemorySize,
                         GEMM_SMEM);

    // ---- weight prep: batched transpose to [N,K] fp16 (6 launches) ----
    {
        dim3 blk(32, 8);
        dim3 gEE(EMB/32, EMB/32, DEPTH);
        transpose_half_batch<<<gEE, blk>>>(Wq, pw + OFF_Q, EMB, EMB,
                                           (size_t)EMB*EMB, LSTRIDE);
        transpose_half_batch<<<gEE, blk>>>(Wk, pw + OFF_K, EMB, EMB,
                                           (size_t)EMB*EMB, LSTRIDE);
        transpose_half_batch<<<gEE, blk>>>(Wv, pw + OFF_V, EMB, EMB,
                                           (size_t)EMB*EMB, LSTRIDE);
        transpose_half_batch<<<gEE, blk>>>(Wo, pw + OFF_O, EMB, EMB,
                                           (size_t)EMB*EMB, LSTRIDE);
        dim3 g1(FF/32, EMB/32, DEPTH);
        transpose_half_batch<<<g1, blk>>>(W1, pw + OFF_W1, EMB, FF,
                                          (size_t)EMB*FF, LSTRIDE);
        dim3 g2(EMB/32, FF/32, DEPTH);
        transpose_half_batch<<<g2, blk>>>(W2, pw + OFF_W2, FF, EMB,
                                          (size_t)FF*EMB, LSTRIDE);
        tohalf_only<<<(EMB*EMB + 255)/256, 256>>>(conv_w, pcw, EMB*EMB);
    }

    // ---- patch embedding ----
    im2col_kernel<<<(PROWS*EMB + 255)/256, 256>>>(x, pimhi, pimlo);
    gemm_hmma<<<dim3(EMB/BN, PROWS/BM), 256, GEMM_SMEM>>>(
        pimhi, pimlo, pcw, conv_b, pt, nullptr, nullptr, PROWS, EMB, EMB, 0);
    embed_kernel<<<(ROWS*EMB + 255)/256, 256>>>(pt, cls_tok, pos_emb,
                                                ph, phhi, phlo);

    const int mtiles = (ROWS + BM - 1) / BM;   // 50
    const dim3 gQKV(QS/BN, mtiles);            // 18 x 50
    const dim3 gE(EMB/BN,  mtiles);            // 6 x 50
    const dim3 gF1(FF/BN,  mtiles);            // 24 x 50
    const dim3 gAT(7, BATCH*NHEAD);

    for (int l = 0; l < DEPTH; l++) {
        size_t base = (size_t)l * LSTRIDE;
        const __half* qkvw = pw + base + OFF_Q;   // [2304, 768]
        const __half* ow   = pw + base + OFF_O;
        const __half* w1w  = pw + base + OFF_W1;
        const __half* w2w  = pw + base + OFF_W2;
        const float* bol= bo + (size_t)l*EMB;
        const float* g1 = ln1_g + (size_t)l*EMB;
        const float* be1= ln1_b + (size_t)l*EMB;
        const float* bb1= b1 + (size_t)l*FF;
        const float* bb2= b2 + (size_t)l*EMB;
        const float* g2 = ln2_g + (size_t)l*EMB;
        const float* be2= ln2_b + (size_t)l*EMB;

        gemm_hmma<<<gQKV, 256, GEMM_SMEM>>>(phhi, phlo, qkvw, nullptr,
                                            pqkv, nullptr, nullptr,
                                            ROWS, QS, EMB, 0);

        attn_fused<<<gAT, 256>>>(pqkv, pthi, ptlo);

        gemm_hmma<<<gE, 256, GEMM_SMEM>>>(pthi, ptlo, ow, bol,
                                          pt, nullptr, nullptr,
                                          ROWS, EMB, EMB, 0);
        add_ln<<<ROWS, 256>>>(pt, ph, g1, be1, px, pxhi, pxlo);

        gemm_hmma<<<gF1, 256, GEMM_SMEM>>>(pxhi, pxlo, w1w, bb1,
                                           nullptr, pfhi, pflo,
                                           ROWS, FF, EMB, 1);
        gemm_hmma<<<gE, 256, GEMM_SMEM>>>(pfhi, pflo, w2w, bb2,
                                          pt, nullptr, nullptr,
                                          ROWS, EMB, FF, 0);
        add_ln<<<ROWS, 256>>>(pt, px, g2, be2, ph, phhi, phlo);
    }

    cls_ln<<<BATCH, 256>>>(ph, head_g, head_b, pcls);
    head_gemm<<<(BATCH*NCLS + 255)/256, 256>>>(pcls, head_W, head_bias, out);
}

// round 7
// speedup vs baseline: 2.4895x; 1.0616x over previous
#include <cuda_runtime.h>
#include <cuda_fp16.h>
#include <cstdint>
#include <cstddef>

// ---------------- Problem constants ----------------
#define IMG   224
#define PATCH 16
#define EMB   768
#define DEPTH 12
#define NHEAD 12
#define HD    64
#define FF    3072
#define NCLS  1000
#define BATCH 32
#define NP    196
#define NTOK  197
#define ROWS  (BATCH * NTOK) // 6304
#define PROWS (BATCH * NP)   // 6272
#define EPS   1e-5f
#define QS    2304           // fused qkv row stride

// weight layout (per layer, element offsets). Q,K,V contiguous -> fused QKV.
#define OFF_Q   0
#define OFF_K   589824
#define OFF_V   1179648
#define OFF_O   1769472
#define OFF_W1  2359296
#define OFF_W2  4718592
#define LSTRIDE 7077888
#define WTOTAL  (LSTRIDE * DEPTH)

// ---------------- Scratch ----------------
__device__ float g_h  [ROWS * EMB];     // layer activation fp32 (residual trunk)
__device__ float g_x  [ROWS * EMB];     // post-LN1 fp32
__device__ float g_t  [ROWS * EMB];     // O-proj / FF2 / conv out fp32
__device__ float g_qkv[ROWS * QS];      // fused qkv fp32
__device__ float g_cls[BATCH * EMB];
__device__ __half g_hh [ROWS * EMB];    // fp16 copies (GEMM A operands)
__device__ __half g_xh [ROWS * EMB];
__device__ __half g_th [ROWS * EMB];
__device__ __half g_fh [ROWS * FF];
__device__ __half g_imh[PROWS * EMB];
__device__ __half g_w  [WTOTAL];        // weights fp16, [N,K]
__device__ __half g_cw [EMB * EMB];

// ---------------- helpers ----------------
__device__ __forceinline__ uint32_t smem_u32(const void* p) {
    uint32_t a;
    asm("{ .reg .u64 t; cvta.to.shared.u64 t, %1; cvt.u32.u64 %0, t; }"
        : "=r"(a) : "l"(p));
    return a;
}
__device__ __forceinline__ void ldm_x4(uint32_t (&r)[4], uint32_t addr) {
    asm volatile("ldmatrix.sync.aligned.m8n8.x4.shared.b16 {%0,%1,%2,%3}, [%4];"
                 : "=r"(r[0]), "=r"(r[1]), "=r"(r[2]), "=r"(r[3]) : "r"(addr));
}
__device__ __forceinline__ void mma_f16(float (&d)[4], const uint32_t (&a)[4],
                                        const uint32_t (&b)[2]) {
    asm volatile("mma.sync.aligned.m16n8k16.row.col.f32.f16.f16.f32 "
                 "{%0,%1,%2,%3}, {%4,%5,%6,%7}, {%8,%9}, {%0,%1,%2,%3};"
                 : "+f"(d[0]), "+f"(d[1]), "+f"(d[2]), "+f"(d[3])
                 : "r"(a[0]), "r"(a[1]), "r"(a[2]), "r"(a[3]),
                   "r"(b[0]), "r"(b[1]));
}
__device__ __forceinline__ uint32_t pack_h2(float x, float y) {
    __half2 h = __floats2half2_rn(x, y);
    return *reinterpret_cast<uint32_t*>(&h);
}

// ---------------- weight prep: transpose [K,N] -> [N,K], fp16 ---------------
__global__ void transpose_half_batch(const float* __restrict__ W,
                                     __half* __restrict__ out,
                                     int K, int N,
                                     size_t w_lstride, size_t o_lstride)
{
    __shared__ float t[32][33];
    const int layer = blockIdx.z;
    W   += (size_t)layer * w_lstride;
    out += (size_t)layer * o_lstride;
    int nb = blockIdx.x * 32, kb = blockIdx.y * 32;
    int tx = threadIdx.x, ty = threadIdx.y;
    #pragma unroll
    for (int j = ty; j < 32; j += 8)
        t[j][tx] = W[(size_t)(kb + j) * N + nb + tx];
    __syncthreads();
    #pragma unroll
    for (int j = ty; j < 32; j += 8)
        out[(size_t)(nb + j) * K + kb + tx] = __float2half_rn(t[tx][j]);
}

__global__ void tohalf_only(const float* __restrict__ W,
                            __half* __restrict__ out, int n)
{
    int i = blockIdx.x * blockDim.x + threadIdx.x;
    if (i < n) out[i] = __float2half_rn(W[i]);
}

// ---------------- pipelined HMMA GEMM (single-pass fp16, fp32 accum) --------
// C[M,N] = A[M,K] @ B[N,K]^T
#define BM 128
#define BN 128
#define BK 32
#define ARR_B 10240                 // 128 rows * 80 B
#define STAGE_B (2 * ARR_B)         // A, B
#define NSTAGE 3
#define GEMM_SMEM (NSTAGE * STAGE_B)  // 61440 B

__global__ __launch_bounds__(256)
void gemm_hmma(const __half* __restrict__ A,
               const __half* __restrict__ B,
               const float* __restrict__ bias,
               float* __restrict__ Cf,
               __half* __restrict__ Ch,
               int M, int N, int K, int do_relu)
{
    extern __shared__ __align__(16) unsigned char dsm[];
    const uint32_t smb = smem_u32(dsm);
    const int tid  = threadIdx.x;
    const int lane = tid & 31;
    const int wid  = tid >> 5;
    const int wm   = wid & 1;
    const int wn   = wid >> 1;
    const int row0 = blockIdx.y * BM;
    const int col0 = blockIdx.x * BN;

    float acc[4][4][4] = {};

    auto load_stage = [&](int s, int kt) {
        #pragma unroll
        for (int l = 0; l < 4; l++) {
            int idx = tid + l * 256;     // 0..1023
            int arr = idx >> 9;          // 0 A, 1 B
            int w   = idx & 511;
            int r   = w >> 2;
            int q   = w & 3;
            int row = (arr ? col0 : row0) + r;
            const __half* src = (arr ? B : A) + (size_t)row * K + kt + q * 8;
            int bytes = (!arr && row >= M) ? 0 : 16;
            uint32_t dst = smb + (uint32_t)s * STAGE_B + (uint32_t)arr * ARR_B
                         + (uint32_t)r * 80u + (uint32_t)q * 16u;
            asm volatile("cp.async.cg.shared.global [%0], [%1], 16, %2;"
                         :: "r"(dst), "l"(src), "r"(bytes) : "memory");
        }
        asm volatile("cp.async.commit_group;" ::: "memory");
    };

    auto compute_stage = [&](int s) {
        const uint32_t uA = smb + (uint32_t)s * STAGE_B;
        const uint32_t uB = uA + ARR_B;
        #pragma unroll
        for (int kk = 0; kk < 2; kk++) {
            const uint32_t kcb = (kk * 16 + ((lane >> 4) << 3)) * 2;
            uint32_t af[4][4];
            uint32_t bf[4][2];
            #pragma unroll
            for (int mi = 0; mi < 4; mi++) {
                uint32_t off = (uint32_t)(wm * 64 + mi * 16 + (lane & 15)) * 80u + kcb;
                ldm_x4(af[mi], uA + off);
            }
            #pragma unroll
            for (int g = 0; g < 2; g++) {
                uint32_t off = (uint32_t)(wn * 32 + g * 16 + (lane & 15)) * 80u + kcb;
                uint32_t tb[4];
                ldm_x4(tb, uB + off);
                bf[g*2+0][0] = tb[0]; bf[g*2+0][1] = tb[2];
                bf[g*2+1][0] = tb[1]; bf[g*2+1][1] = tb[3];
            }
            #pragma unroll
            for (int mi = 0; mi < 4; mi++)
                #pragma unroll
                for (int n = 0; n < 4; n++)
                    mma_f16(acc[mi][n], af[mi], bf[n]);
        }
    };

    const int nk = K / BK;      // >= 2 always (K = 768 or 3072)
    load_stage(0, 0);
    load_stage(1, BK);
    for (int i = 0; i < nk; i++) {
        asm volatile("cp.async.wait_group 1;" ::: "memory");
        __syncthreads();
        compute_stage(i % NSTAGE);
        if (i + 2 < nk)
            load_stage((i + 2) % NSTAGE, (i + 2) * BK);
        else
            asm volatile("cp.async.commit_group;" ::: "memory"); // keep group count in step
    }

    // ---- epilogue ----
    const bool hb = (bias != nullptr);
    #pragma unroll
    for (int mi = 0; mi < 4; mi++) {
        #pragma unroll
        for (int n = 0; n < 4; n++) {
            int gc = col0 + wn * 32 + n * 8 + (lane & 3) * 2;
            float bx = 0.f, by = 0.f;
            if (hb) { bx = bias[gc]; by = bias[gc + 1]; }
            #pragma unroll
            for (int h = 0; h < 2; h++) {
                int gr = row0 + wm * 64 + mi * 16 + (lane >> 2) + h * 8;
                if (gr >= M) continue;
                float ox = acc[mi][n][h * 2 + 0] + bx;
                float oy = acc[mi][n][h * 2 + 1] + by;
                if (do_relu) { ox = fmaxf(ox, 0.f); oy = fmaxf(oy, 0.f); }
                size_t o = (size_t)gr * N + gc;
                if (Cf)
                    *reinterpret_cast<float2*>(&Cf[o]) = make_float2(ox, oy);
                if (Ch)
                    *reinterpret_cast<uint32_t*>(&Ch[o]) = pack_h2(ox, oy);
            }
        }
    }
}

// ---------------- im2col (emits fp16) ---------------------------------------
__global__ void im2col_kernel(const float* __restrict__ x,
                              __half* __restrict__ ho)
{
    int idx = blockIdx.x * blockDim.x + threadIdx.x;
    if (idx >= PROWS * EMB) return;
    int row = idx / EMB;
    int k   = idx % EMB;
    int b   = row / NP;
    int p   = row % NP;
    int py  = p / 14, px = p % 14;
    int c   = k / 256;
    int r2  = k % 256;
    int ph  = r2 / PATCH, pw = r2 % PATCH;
    float v = x[(((size_t)b * 3 + c) * IMG + (py * PATCH + ph)) * IMG
                + (px * PATCH + pw)];
    ho[idx] = __float2half_rn(v);
}

__global__ void embed_kernel(const float* __restrict__ patch,
                             const float* __restrict__ cls_tok,
                             const float* __restrict__ pos,
                             float* __restrict__ h,
                             __half* __restrict__ hh)
{
    int idx = blockIdx.x * blockDim.x + threadIdx.x;
    if (idx >= ROWS * EMB) return;
    int row = idx / EMB;
    int e   = idx % EMB;
    int b   = row / NTOK;
    int n   = row % NTOK;
    float base = (n == 0) ? cls_tok[e]
                          : patch[((size_t)b * NP + (n - 1)) * EMB + e];
    float v = base + pos[n * EMB + e];
    h[idx]  = v;
    hh[idx] = __float2half_rn(v);
}

// ---------------- fused attention: scores + softmax + AV ---------------------
// grid(7 q-blocks, B*H), 256 threads. scores kept in smem.
#define SCP 224   // score row stride; cols 197..223 zero-padded for AV tail tile

__global__ __launch_bounds__(256)
void attn_fused(const float* __restrict__ qkv, __half* __restrict__ th)
{
    __shared__ __align__(16) float Qs[32][68];
    __shared__ __align__(16) float KV[32][68];
    __shared__ float sc[32][SCP];

    const int bh = blockIdx.y;
    const int b  = bh / NHEAD;
    const int hh = bh % NHEAD;
    const int q0 = blockIdx.x * 32;
    const float scale = 0.036084391824f;   // 1/sqrt(768)

    const int tid  = threadIdx.x;
    const int lane = tid & 31;
    const int wrp  = tid >> 5;
    const int tx   = tid & 15;
    const int ty   = tid >> 4;

    const float* Qb = qkv + (size_t)b * NTOK * QS + hh * HD;
    const float* Kb = Qb + 768;
    const float* Vb = Qb + 1536;

    // load Q tile
    #pragma unroll
    for (int l = 0; l < 2; l++) {
        int idx = tid + l * 256;
        int r   = idx >> 4;
        int c4  = (idx & 15) << 2;
        float4 vq = make_float4(0.f, 0.f, 0.f, 0.f);
        if (q0 + r < NTOK)
            vq = *reinterpret_cast<const float4*>(&Qb[(size_t)(q0 + r) * QS + c4]);
        Qs[r][c4+0]=vq.x; Qs[r][c4+1]=vq.y; Qs[r][c4+2]=vq.z; Qs[r][c4+3]=vq.w;
    }
    // zero the tail columns of sc (cols 192..223): AV tail tile multiplies by 0
    for (int i = tid; i < 32 * 32; i += 256)
        sc[i >> 5][192 + (i & 31)] = 0.f;
    __syncthreads();

    // ---- phase 1: scores ----
    for (int kt = 0; kt < NTOK; kt += 32) {
        #pragma unroll
        for (int l = 0; l < 2; l++) {
            int idx = tid + l * 256;
            int r   = idx >> 4;
            int c4  = (idx & 15) << 2;
            float4 vk = make_float4(0.f, 0.f, 0.f, 0.f);
            if (kt + r < NTOK)
                vk = *reinterpret_cast<const float4*>(&Kb[(size_t)(kt + r) * QS + c4]);
            KV[r][c4+0]=vk.x; KV[r][c4+1]=vk.y; KV[r][c4+2]=vk.z; KV[r][c4+3]=vk.w;
        }
        __syncthreads();

        float acc[2][2] = {{0.f,0.f},{0.f,0.f}};
        #pragma unroll
        for (int kk = 0; kk < HD; kk++) {
            float a0 = Qs[ty*2+0][kk], a1 = Qs[ty*2+1][kk];
            float b0 = KV[tx*2+0][kk], b1 = KV[tx*2+1][kk];
            acc[0][0] = fmaf(a0,b0,acc[0][0]);
            acc[0][1] = fmaf(a0,b1,acc[0][1]);
            acc[1][0] = fmaf(a1,b0,acc[1][0]);
            acc[1][1] = fmaf(a1,b1,acc[1][1]);
        }
        #pragma unroll
        for (int i = 0; i < 2; i++)
            #pragma unroll
            for (int j = 0; j < 2; j++) {
                int kc = kt + tx*2 + j;
                if (kc < NTOK) sc[ty*2+i][kc] = acc[i][j] * scale;
            }
        __syncthreads();
    }

    // ---- phase 2: softmax (warp w: rows w, w+8, w+16, w+24) ----
    #pragma unroll
    for (int rr = 0; rr < 4; rr++) {
        int row = wrp + rr * 8;
        float vals[7];
        float mx = -1e30f;
        #pragma unroll
        for (int i = 0; i < 7; i++) {
            int c = i * 32 + lane;
            vals[i] = (c < NTOK) ? sc[row][c] : -1e30f;
            mx = fmaxf(mx, vals[i]);
        }
        #pragma unroll
        for (int o = 16; o; o >>= 1) mx = fmaxf(mx, __shfl_xor_sync(0xffffffffu, mx, o));
        float s = 0.f;
        #pragma unroll
        for (int i = 0; i < 7; i++) { vals[i] = expf(vals[i] - mx); s += vals[i]; }
        #pragma unroll
        for (int o = 16; o; o >>= 1) s += __shfl_xor_sync(0xffffffffu, s, o);
        float inv = 1.f / s;
        #pragma unroll
        for (int i = 0; i < 7; i++) {
            int c = i * 32 + lane;
            if (c < NTOK) sc[row][c] = vals[i] * inv;
        }
    }
    __syncthreads();

    // ---- phase 3: out = attn @ V ----
    float acc[2][4] = {};
    for (int kt = 0; kt < NTOK; kt += 32) {
        #pragma unroll
        for (int l = 0; l < 2; l++) {
            int idx = tid + l * 256;
            int r   = idx >> 4;
            int c4  = (idx & 15) << 2;
            float4 vv = make_float4(0.f, 0.f, 0.f, 0.f);
            if (kt + r < NTOK)
                vv = *reinterpret_cast<const float4*>(&Vb[(size_t)(kt + r) * QS + c4]);
            KV[r][c4+0]=vv.x; KV[r][c4+1]=vv.y; KV[r][c4+2]=vv.z; KV[r][c4+3]=vv.w;
        }
        __syncthreads();

        #pragma unroll
        for (int kk = 0; kk < 32; kk++) {
            float a0 = sc[ty*2+0][kt+kk];
            float a1 = sc[ty*2+1][kt+kk];
            float rb[4];
            *reinterpret_cast<float4*>(rb) =
                *reinterpret_cast<const float4*>(&KV[kk][tx*4]);
            #pragma unroll
            for (int j = 0; j < 4; j++) {
                acc[0][j] = fmaf(a0, rb[j], acc[0][j]);
                acc[1][j] = fmaf(a1, rb[j], acc[1][j]);
            }
        }
        __syncthreads();
    }

    #pragma unroll
    for (int i = 0; i < 2; i++) {
        int qr = q0 + ty*2 + i;
        if (qr >= NTOK) continue;
        size_t o = ((size_t)b * NTOK + qr) * EMB + hh * HD + tx * 4;
        uint2 hp;
        hp.x = pack_h2(acc[i][0], acc[i][1]);
        hp.y = pack_h2(acc[i][2], acc[i][3]);
        *reinterpret_cast<uint2*>(&th[o]) = hp;
    }
}

// ---------------- fused residual add + LayerNorm (+ fp16 emit) --------------
__global__ __launch_bounds__(256)
void add_ln(const float* __restrict__ a, const float* __restrict__ b,
            const float* __restrict__ g, const float* __restrict__ be,
            float* __restrict__ out, __half* __restrict__ oh)
{
    const int r   = blockIdx.x;
    const int tid = threadIdx.x;
    float v[3];
    float s = 0.f, q = 0.f;
    #pragma unroll
    for (int t = 0; t < 3; t++) {
        int c = tid + t * 256;
        v[t] = a[(size_t)r * EMB + c] + b[(size_t)r * EMB + c];
        s += v[t];
        q += v[t] * v[t];
    }
    #pragma unroll
    for (int o = 16; o; o >>= 1) {
        s += __shfl_xor_sync(0xffffffffu, s, o);
        q += __shfl_xor_sync(0xffffffffu, q, o);
    }
    __shared__ float red[2][8];
    int w = tid >> 5, lane = tid & 31;
    if (lane == 0) { red[0][w] = s; red[1][w] = q; }
    __syncthreads();
    s = 0.f; q = 0.f;
    #pragma unroll
    for (int i = 0; i < 8; i++) { s += red[0][i]; q += red[1][i]; }
    float mean = s * (1.f / EMB);
    float var  = q * (1.f / EMB) - mean * mean;
    float rstd = rsqrtf(var + EPS);
    #pragma unroll
    for (int t = 0; t < 3; t++) {
        int c = tid + t * 256;
        float o = (v[t] - mean) * rstd * g[c] + be[c];
        size_t idx = (size_t)r * EMB + c;
        out[idx] = o;
        oh[idx]  = __float2half_rn(o);
    }
}

__global__ __launch_bounds__(256)
void cls_ln(const float* __restrict__ h, const float* __restrict__ g,
            const float* __restrict__ be, float* __restrict__ out)
{
    const int b   = blockIdx.x;
    const int tid = threadIdx.x;
    const float* row = h + (size_t)b * NTOK * EMB;
    float v[3];
    float s = 0.f, q = 0.f;
    #pragma unroll
    for (int t = 0; t < 3; t++) {
        int c = tid + t * 256;
        v[t] = row[c];
        s += v[t];
        q += v[t] * v[t];
    }
    #pragma unroll
    for (int o = 16; o; o >>= 1) {
        s += __shfl_xor_sync(0xffffffffu, s, o);
        q += __shfl_xor_sync(0xffffffffu, q, o);
    }
    __shared__ float red[2][8];
    int w = tid >> 5, lane = tid & 31;
    if (lane == 0) { red[0][w] = s; red[1][w] = q; }
    __syncthreads();
    s = 0.f; q = 0.f;
    #pragma unroll
    for (int i = 0; i < 8; i++) { s += red[0][i]; q += red[1][i]; }
    float mean = s * (1.f / EMB);
    float var  = q * (1.f / EMB) - mean * mean;
    float rstd = rsqrtf(var + EPS);
    #pragma unroll
    for (int t = 0; t < 3; t++) {
        int c = tid + t * 256;
        out[(size_t)b * EMB + c] = (v[t] - mean) * rstd * g[c] + be[c];
    }
}

// ---------------- classifier head -------------------------------------------
__global__ __launch_bounds__(256)
void head_gemm(const float* __restrict__ cls, const float* __restrict__ W,
               const float* __restrict__ bias, float* __restrict__ out)
{
    int idx = blockIdx.x * blockDim.x + threadIdx.x;
    if (idx >= BATCH * NCLS) return;
    int b = idx / NCLS;
    int n = idx % NCLS;
    float s = bias[n];
    const float* c = cls + (size_t)b * EMB;
    for (int k = 0; k < EMB; k++)
        s = fmaf(c[k], W[(size_t)k * NCLS + n], s);
    out[idx] = s;
}

// ---------------- driver -----------------------------------------------------
extern "C" void kernel_launch(void* const* d_in, const int* in_sizes, int n_in,
                              void* d_out, int out_size)
{
    const float* x        = (const float*)d_in[0];
    const float* conv_w   = (const float*)d_in[1];
    const float* conv_b   = (const float*)d_in[2];
    const float* cls_tok  = (const float*)d_in[3];
    const float* pos_emb  = (const float*)d_in[4];
    const float* Wq       = (const float*)d_in[5];
    const float* Wk       = (const float*)d_in[6];
    const float* Wv       = (const float*)d_in[7];
    const float* Wo       = (const float*)d_in[8];
    const float* bo       = (const float*)d_in[9];
    const float* ln1_g    = (const float*)d_in[10];
    const float* ln1_b    = (const float*)d_in[11];
    const float* W1       = (const float*)d_in[12];
    const float* b1       = (const float*)d_in[13];
    const float* W2       = (const float*)d_in[14];
    const float* b2       = (const float*)d_in[15];
    const float* ln2_g    = (const float*)d_in[16];
    const float* ln2_b    = (const float*)d_in[17];
    const float* head_g   = (const float*)d_in[18];
    const float* head_b   = (const float*)d_in[19];
    const float* head_W   = (const float*)d_in[20];
    const float* head_bias= (const float*)d_in[21];
    float* out = (float*)d_out;

    float *ph, *px, *pt, *pqkv, *pcls;
    __half *phh, *pxh, *pth, *pfh, *pimh, *pw, *pcw;
    cudaGetSymbolAddress((void**)&ph,   g_h);
    cudaGetSymbolAddress((void**)&px,   g_x);
    cudaGetSymbolAddress((void**)&pt,   g_t);
    cudaGetSymbolAddress((void**)&pqkv, g_qkv);
    cudaGetSymbolAddress((void**)&pcls, g_cls);
    cudaGetSymbolAddress((void**)&phh,  g_hh);
    cudaGetSymbolAddress((void**)&pxh,  g_xh);
    cudaGetSymbolAddress((void**)&pth,  g_th);
    cudaGetSymbolAddress((void**)&pfh,  g_fh);
    cudaGetSymbolAddress((void**)&pimh, g_imh);
    cudaGetSymbolAddress((void**)&pw,   g_w);
    cudaGetSymbolAddress((void**)&pcw,  g_cw);

    cudaFuncSetAttribute(gemm_hmma, cudaFuncAttributeMaxDynamicSharedMemorySize,
                         GEMM_SMEM);

    // ---- weight prep: batched transpose to [N,K] fp16 ----
    {
        dim3 blk(32, 8);
        dim3 gEE(EMB/32, EMB/32, DEPTH);
        transpose_half_batch<<<gEE, blk>>>(Wq, pw + OFF_Q, EMB, EMB,
                                           (size_t)EMB*EMB, LSTRIDE);
        transpose_half_batch<<<gEE, blk>>>(Wk, pw + OFF_K, EMB, EMB,
                                           (size_t)EMB*EMB, LSTRIDE);
        transpose_half_batch<<<gEE, blk>>>(Wv, pw + OFF_V, EMB, EMB,
                                           (size_t)EMB*EMB, LSTRIDE);
        transpose_half_batch<<<gEE, blk>>>(Wo, pw + OFF_O, EMB, EMB,
                                           (size_t)EMB*EMB, LSTRIDE);
        dim3 g1(FF/32, EMB/32, DEPTH);
        transpose_half_batch<<<g1, blk>>>(W1, pw + OFF_W1, EMB, FF,
                                          (size_t)EMB*FF, LSTRIDE);
        dim3 g2(EMB/32, FF/32, DEPTH);
        transpose_half_batch<<<g2, blk>>>(W2, pw + OFF_W2, FF, EMB,
                                          (size_t)FF*EMB, LSTRIDE);
        tohalf_only<<<(EMB*EMB + 255)/256, 256>>>(conv_w, pcw, EMB*EMB);
    }

    // ---- patch embedding ----
    im2col_kernel<<<(PROWS*EMB + 255)/256, 256>>>(x, pimh);
    gemm_hmma<<<dim3(EMB/BN, PROWS/BM), 256, GEMM_SMEM>>>(
        pimh, pcw, conv_b, pt, nullptr, PROWS, EMB, EMB, 0);
    embed_kernel<<<(ROWS*EMB + 255)/256, 256>>>(pt, cls_tok, pos_emb, ph, phh);

    const int mtiles = (ROWS + BM - 1) / BM;   // 50
    const dim3 gQKV(QS/BN, mtiles);            // 18 x 50
    const dim3 gE(EMB/BN,  mtiles);            // 6 x 50
    const dim3 gF1(FF/BN,  mtiles);            // 24 x 50
    const dim3 gAT(7, BATCH*NHEAD);

    for (int l = 0; l < DEPTH; l++) {
        size_t base = (size_t)l * LSTRIDE;
        const __half* qkvw = pw + base + OFF_Q;   // [2304, 768]
        const __half* ow   = pw + base + OFF_O;
        const __half* w1w  = pw + base + OFF_W1;
        const __half* w2w  = pw + base + OFF_W2;
        const float* bol= bo + (size_t)l*EMB;
        const float* g1 = ln1_g + (size_t)l*EMB;
        const float* be1= ln1_b + (size_t)l*EMB;
        const float* bb1= b1 + (size_t)l*FF;
        const float* bb2= b2 + (size_t)l*EMB;
        const float* g2 = ln2_g + (size_t)l*EMB;
        const float* be2= ln2_b + (size_t)l*EMB;

        gemm_hmma<<<gQKV, 256, GEMM_SMEM>>>(phh, qkvw, nullptr,
                                            pqkv, nullptr, ROWS, QS, EMB, 0);

        attn_fused<<<gAT, 256>>>(pqkv, pth);

        gemm_hmma<<<gE, 256, GEMM_SMEM>>>(pth, ow, bol,
                                          pt, nullptr, ROWS, EMB, EMB, 0);
        add_ln<<<ROWS, 256>>>(pt, ph, g1, be1, px, pxh);

        gemm_hmma<<<gF1, 256, GEMM_SMEM>>>(pxh, w1w, bb1,
                                           nullptr, pfh, ROWS, FF, EMB, 1);
        gemm_hmma<<<gE, 256, GEMM_SMEM>>>(pfh, w2w, bb2,
                                          pt, nullptr, ROWS, EMB, FF, 0);
        add_ln<<<ROWS, 256>>>(pt, px, g2, be2, ph, phh);
    }

    cls_ln<<<BATCH, 256>>>(ph, head_g, head_b, pcls);
    head_gemm<<<(BATCH*NCLS + 255)/256, 256>>>(pcls, head_W, head_bias, out);
}

// round 8
// speedup vs baseline: 3.8237x; 1.5359x over previous
#include <cuda_runtime.h>
#include <cuda_fp16.h>
#include <cstdint>
#include <cstddef>

// ---------------- Problem constants ----------------
#define IMG   224
#define PATCH 16
#define EMB   768
#define DEPTH 12
#define NHEAD 12
#define HD    64
#define FF    3072
#define NCLS  1000
#define BATCH 32
#define NP    196
#define NTOK  197
#define ROWS  (BATCH * NTOK) // 6304
#define PROWS (BATCH * NP)   // 6272
#define EPS   1e-5f
#define QS    2304           // fused qkv row stride

// weight layout (per layer, element offsets). Q,K,V contiguous -> fused QKV.
#define OFF_Q   0
#define OFF_K   589824
#define OFF_V   1179648
#define OFF_O   1769472
#define OFF_W1  2359296
#define OFF_W2  4718592
#define LSTRIDE 7077888
#define WTOTAL  (LSTRIDE * DEPTH)

// ---------------- Scratch ----------------
__device__ float g_h  [ROWS * EMB];     // layer activation fp32 (residual trunk)
__device__ float g_x  [ROWS * EMB];     // post-LN1 fp32
__device__ float g_t  [ROWS * EMB];     // O-proj / FF2 / conv out fp32
__device__ float g_qkv[ROWS * QS];      // fused qkv fp32
__device__ float g_cls[BATCH * EMB];
__device__ __half g_hh [ROWS * EMB];    // fp16 copies (GEMM A operands)
__device__ __half g_xh [ROWS * EMB];
__device__ __half g_th [ROWS * EMB];
__device__ __half g_fh [ROWS * FF];
__device__ __half g_imh[PROWS * EMB];
__device__ __half g_w  [WTOTAL];        // weights fp16, [N,K]
__device__ __half g_cw [EMB * EMB];

// ---------------- helpers ----------------
__device__ __forceinline__ uint32_t smem_u32(const void* p) {
    uint32_t a;
    asm("{ .reg .u64 t; cvta.to.shared.u64 t, %1; cvt.u32.u64 %0, t; }"
        : "=r"(a) : "l"(p));
    return a;
}
__device__ __forceinline__ void ldm_x4(uint32_t (&r)[4], uint32_t addr) {
    asm volatile("ldmatrix.sync.aligned.m8n8.x4.shared.b16 {%0,%1,%2,%3}, [%4];"
                 : "=r"(r[0]), "=r"(r[1]), "=r"(r[2]), "=r"(r[3]) : "r"(addr));
}
__device__ __forceinline__ void mma_f16(float (&d)[4], const uint32_t (&a)[4],
                                        const uint32_t (&b)[2]) {
    asm volatile("mma.sync.aligned.m16n8k16.row.col.f32.f16.f16.f32 "
                 "{%0,%1,%2,%3}, {%4,%5,%6,%7}, {%8,%9}, {%0,%1,%2,%3};"
                 : "+f"(d[0]), "+f"(d[1]), "+f"(d[2]), "+f"(d[3])
                 : "r"(a[0]), "r"(a[1]), "r"(a[2]), "r"(a[3]),
                   "r"(b[0]), "r"(b[1]));
}
__device__ __forceinline__ uint32_t pack_h2(float x, float y) {
    __half2 h = __floats2half2_rn(x, y);
    return *reinterpret_cast<uint32_t*>(&h);
}

// ---------------- weight prep: transpose [K,N] -> [N,K], fp16 ---------------
__global__ void transpose_half_batch(const float* __restrict__ W,
                                     __half* __restrict__ out,
                                     int K, int N,
                                     size_t w_lstride, size_t o_lstride)
{
    __shared__ float t[32][33];
    const int layer = blockIdx.z;
    W   += (size_t)layer * w_lstride;
    out += (size_t)layer * o_lstride;
    int nb = blockIdx.x * 32, kb = blockIdx.y * 32;
    int tx = threadIdx.x, ty = threadIdx.y;
    #pragma unroll
    for (int j = ty; j < 32; j += 8)
        t[j][tx] = W[(size_t)(kb + j) * N + nb + tx];
    __syncthreads();
    #pragma unroll
    for (int j = ty; j < 32; j += 8)
        out[(size_t)(nb + j) * K + kb + tx] = __float2half_rn(t[tx][j]);
}

__global__ void tohalf_only(const float* __restrict__ W,
                            __half* __restrict__ out, int n)
{
    int i = blockIdx.x * blockDim.x + threadIdx.x;
    if (i < n) out[i] = __float2half_rn(W[i]);
}

// ---------------- pipelined HMMA GEMM (single-pass fp16, fp32 accum) --------
// C[M,N] = A[M,K] @ B[N,K]^T
#define BM 128
#define BN 128
#define BK 32
#define ARR_B 10240                 // 128 rows * 80 B
#define STAGE_B (2 * ARR_B)         // A, B
#define NSTAGE 2
#define GEMM_SMEM (NSTAGE * STAGE_B)  // 40960 B

__global__ __launch_bounds__(256, 2)
void gemm_hmma(const __half* __restrict__ A,
               const __half* __restrict__ B,
               const float* __restrict__ bias,
               float* __restrict__ Cf,
               __half* __restrict__ Ch,
               int M, int N, int K, int do_relu)
{
    extern __shared__ __align__(16) unsigned char dsm[];
    const uint32_t smb = smem_u32(dsm);
    const int tid  = threadIdx.x;
    const int lane = tid & 31;
    const int wid  = tid >> 5;
    const int wm   = wid & 1;
    const int wn   = wid >> 1;
    const int row0 = blockIdx.y * BM;
    const int col0 = blockIdx.x * BN;

    float acc[4][4][4] = {};

    auto load_stage = [&](int s, int kt) {
        #pragma unroll
        for (int l = 0; l < 4; l++) {
            int idx = tid + l * 256;     // 0..1023
            int arr = idx >> 9;          // 0 A, 1 B
            int w   = idx & 511;
            int r   = w >> 2;
            int q   = w & 3;
            int row = (arr ? col0 : row0) + r;
            const __half* src = (arr ? B : A) + (size_t)row * K + kt + q * 8;
            int bytes = (!arr && row >= M) ? 0 : 16;
            uint32_t dst = smb + (uint32_t)s * STAGE_B + (uint32_t)arr * ARR_B
                         + (uint32_t)r * 80u + (uint32_t)q * 16u;
            asm volatile("cp.async.cg.shared.global [%0], [%1], 16, %2;"
                         :: "r"(dst), "l"(src), "r"(bytes) : "memory");
        }
        asm volatile("cp.async.commit_group;" ::: "memory");
    };

    auto compute_stage = [&](int s) {
        const uint32_t uA = smb + (uint32_t)s * STAGE_B;
        const uint32_t uB = uA + ARR_B;
        #pragma unroll
        for (int kk = 0; kk < 2; kk++) {
            const uint32_t kcb = (kk * 16 + ((lane >> 4) << 3)) * 2;
            uint32_t af[4][4];
            uint32_t bf[4][2];
            #pragma unroll
            for (int mi = 0; mi < 4; mi++) {
                uint32_t off = (uint32_t)(wm * 64 + mi * 16 + (lane & 15)) * 80u + kcb;
                ldm_x4(af[mi], uA + off);
            }
            #pragma unroll
            for (int g = 0; g < 2; g++) {
                uint32_t off = (uint32_t)(wn * 32 + g * 16 + (lane & 15)) * 80u + kcb;
                uint32_t tb[4];
                ldm_x4(tb, uB + off);
                bf[g*2+0][0] = tb[0]; bf[g*2+0][1] = tb[2];
                bf[g*2+1][0] = tb[1]; bf[g*2+1][1] = tb[3];
            }
            #pragma unroll
            for (int mi = 0; mi < 4; mi++)
                #pragma unroll
                for (int n = 0; n < 4; n++)
                    mma_f16(acc[mi][n], af[mi], bf[n]);
        }
    };

    const int nk = K / BK;
    load_stage(0, 0);
    for (int i = 0; i < nk; i++) {
        const int cur = i & 1;
        if (i + 1 < nk) {
            load_stage(cur ^ 1, (i + 1) * BK);
            asm volatile("cp.async.wait_group 1;" ::: "memory");
        } else {
            asm volatile("cp.async.wait_group 0;" ::: "memory");
        }
        __syncthreads();
        compute_stage(cur);
        __syncthreads();
    }

    // ---- epilogue ----
    const bool hb = (bias != nullptr);
    #pragma unroll
    for (int mi = 0; mi < 4; mi++) {
        #pragma unroll
        for (int n = 0; n < 4; n++) {
            int gc = col0 + wn * 32 + n * 8 + (lane & 3) * 2;
            float bx = 0.f, by = 0.f;
            if (hb) { bx = bias[gc]; by = bias[gc + 1]; }
            #pragma unroll
            for (int h = 0; h < 2; h++) {
                int gr = row0 + wm * 64 + mi * 16 + (lane >> 2) + h * 8;
                if (gr >= M) continue;
                float ox = acc[mi][n][h * 2 + 0] + bx;
                float oy = acc[mi][n][h * 2 + 1] + by;
                if (do_relu) { ox = fmaxf(ox, 0.f); oy = fmaxf(oy, 0.f); }
                size_t o = (size_t)gr * N + gc;
                if (Cf)
                    *reinterpret_cast<float2*>(&Cf[o]) = make_float2(ox, oy);
                if (Ch)
                    *reinterpret_cast<uint32_t*>(&Ch[o]) = pack_h2(ox, oy);
            }
        }
    }
}

// ---------------- im2col (emits fp16) ---------------------------------------
__global__ void im2col_kernel(const float* __restrict__ x,
                              __half* __restrict__ ho)
{
    int idx = blockIdx.x * blockDim.x + threadIdx.x;
    if (idx >= PROWS * EMB) return;
    int row = idx / EMB;
    int k   = idx % EMB;
    int b   = row / NP;
    int p   = row % NP;
    int py  = p / 14, px = p % 14;
    int c   = k / 256;
    int r2  = k % 256;
    int ph  = r2 / PATCH, pw = r2 % PATCH;
    float v = x[(((size_t)b * 3 + c) * IMG + (py * PATCH + ph)) * IMG
                + (px * PATCH + pw)];
    ho[idx] = __float2half_rn(v);
}

__global__ void embed_kernel(const float* __restrict__ patch,
                             const float* __restrict__ cls_tok,
                             const float* __restrict__ pos,
                             float* __restrict__ h,
                             __half* __restrict__ hh)
{
    int idx = blockIdx.x * blockDim.x + threadIdx.x;
    if (idx >= ROWS * EMB) return;
    int row = idx / EMB;
    int e   = idx % EMB;
    int b   = row / NTOK;
    int n   = row % NTOK;
    float base = (n == 0) ? cls_tok[e]
                          : patch[((size_t)b * NP + (n - 1)) * EMB + e];
    float v = base + pos[n * EMB + e];
    h[idx]  = v;
    hh[idx] = __float2half_rn(v);
}

// ---------------- fused attention v2: 64 q-rows/block, 4x4 thread tiles -----
// dynamic smem: Qs[64][68] | KT/V[4352] | sc[64][260]
#define ATT_QS_STRIDE 68
#define ATT_KT_STRIDE 65
#define ATT_V_STRIDE  68
#define ATT_SC_STRIDE 260
#define ATT_Q_OFF  0
#define ATT_KV_OFF 4352
#define ATT_SC_OFF 8704
#define ATT_SMEM   ((8704 + 64 * ATT_SC_STRIDE) * 4)   // 101376 B

__global__ __launch_bounds__(256, 2)
void attn_fused(const float* __restrict__ qkv, __half* __restrict__ th)
{
    extern __shared__ __align__(16) float sm[];
    float* Qs = sm + ATT_Q_OFF;    // [64][68]
    float* KV = sm + ATT_KV_OFF;   // KT [64 kk][65] in phase1, V [64][68] in phase3
    float* SC = sm + ATT_SC_OFF;   // [64][260]

    const int bh = blockIdx.y;
    const int b  = bh / NHEAD;
    const int hh = bh % NHEAD;
    const int q0 = blockIdx.x * 64;
    const float scale = 0.036084391824f;   // 1/sqrt(768)

    const int tid  = threadIdx.x;
    const int lane = tid & 31;
    const int wrp  = tid >> 5;
    const int tx   = tid & 15;     // 16 col groups of 4
    const int ty   = tid >> 4;     // 16 row groups of 4

    const float* Qb = qkv + (size_t)b * NTOK * QS + hh * HD;
    const float* Kb = Qb + 768;
    const float* Vb = Qb + 1536;

    // ---- load Q tile: 64 rows x 64 (zero-padded rows past NTOK) ----
    #pragma unroll
    for (int l = 0; l < 4; l++) {
        int idx = tid + l * 256;       // 0..1023
        int r   = idx >> 4;            // 0..63
        int c4  = (idx & 15) << 2;
        float4 vq = make_float4(0.f, 0.f, 0.f, 0.f);
        if (q0 + r < NTOK)
            vq = *reinterpret_cast<const float4*>(&Qb[(size_t)(q0 + r) * QS + c4]);
        float* qp = Qs + r * ATT_QS_STRIDE + c4;
        qp[0] = vq.x; qp[1] = vq.y; qp[2] = vq.z; qp[3] = vq.w;
    }
    __syncthreads();

    // ---- phase 1: scores (K stored transposed: KT[kk][krow], stride 65) ----
    for (int kt = 0; kt < 4; kt++) {
        #pragma unroll
        for (int l = 0; l < 4; l++) {
            int idx = tid + l * 256;
            int r   = idx >> 4;        // k row within tile 0..63
            int c4  = (idx & 15) << 2; // head-dim 0..60
            float4 vk = make_float4(0.f, 0.f, 0.f, 0.f);
            int kr = kt * 64 + r;
            if (kr < NTOK)
                vk = *reinterpret_cast<const float4*>(&Kb[(size_t)kr * QS + c4]);
            KV[(c4 + 0) * ATT_KT_STRIDE + r] = vk.x;
            KV[(c4 + 1) * ATT_KT_STRIDE + r] = vk.y;
            KV[(c4 + 2) * ATT_KT_STRIDE + r] = vk.z;
            KV[(c4 + 3) * ATT_KT_STRIDE + r] = vk.w;
        }
        __syncthreads();

        float acc[4][4] = {};
        #pragma unroll 8
        for (int kk = 0; kk < HD; kk++) {
            float aq[4], bk[4];
            #pragma unroll
            for (int i = 0; i < 4; i++)
                aq[i] = Qs[(ty * 4 + i) * ATT_QS_STRIDE + kk];
            #pragma unroll
            for (int j = 0; j < 4; j++)
                bk[j] = KV[kk * ATT_KT_STRIDE + tx * 4 + j];
            #pragma unroll
            for (int i = 0; i < 4; i++)
                #pragma unroll
                for (int j = 0; j < 4; j++)
                    acc[i][j] = fmaf(aq[i], bk[j], acc[i][j]);
        }
        #pragma unroll
        for (int i = 0; i < 4; i++)
            #pragma unroll
            for (int j = 0; j < 4; j++)
                SC[(ty * 4 + i) * ATT_SC_STRIDE + kt * 64 + tx * 4 + j]
                    = acc[i][j] * scale;
        __syncthreads();
    }

    // ---- phase 2: softmax (warp w handles rows w, w+8, ..., w+56) ----
    #pragma unroll
    for (int rr = 0; rr < 8; rr++) {
        int row = wrp + rr * 8;
        float* p = SC + row * ATT_SC_STRIDE;
        float vals[7];
        float mx = -1e30f;
        #pragma unroll
        for (int i = 0; i < 7; i++) {
            int c = i * 32 + lane;
            vals[i] = (c < NTOK) ? p[c] : -1e30f;
            mx = fmaxf(mx, vals[i]);
        }
        #pragma unroll
        for (int o = 16; o; o >>= 1) mx = fmaxf(mx, __shfl_xor_sync(0xffffffffu, mx, o));
        float s = 0.f;
        #pragma unroll
        for (int i = 0; i < 7; i++) { vals[i] = expf(vals[i] - mx); s += vals[i]; }
        #pragma unroll
        for (int o = 16; o; o >>= 1) s += __shfl_xor_sync(0xffffffffu, s, o);
        float inv = 1.f / s;
        #pragma unroll
        for (int i = 0; i < 8; i++) {     // 8 chunks: also zero cols 197..255
            int c = i * 32 + lane;
            p[c] = (c < NTOK && i < 7) ? vals[i] * inv : 0.f;
        }
    }
    __syncthreads();

    // ---- phase 3: out = attn @ V (V natural layout, stride 68) ----
    float oac[4][4] = {};
    for (int kt = 0; kt < 4; kt++) {
        #pragma unroll
        for (int l = 0; l < 4; l++) {
            int idx = tid + l * 256;
            int r   = idx >> 4;
            int c4  = (idx & 15) << 2;
            float4 vv = make_float4(0.f, 0.f, 0.f, 0.f);
            int kr = kt * 64 + r;
            if (kr < NTOK)
                vv = *reinterpret_cast<const float4*>(&Vb[(size_t)kr * QS + c4]);
            *reinterpret_cast<float4*>(&KV[r * ATT_V_STRIDE + c4]) = vv;
        }
        __syncthreads();

        #pragma unroll 8
        for (int kk = 0; kk < 64; kk++) {
            float ap[4];
            #pragma unroll
            for (int i = 0; i < 4; i++)
                ap[i] = SC[(ty * 4 + i) * ATT_SC_STRIDE + kt * 64 + kk];
            float vv[4];
            *reinterpret_cast<float4*>(vv) =
                *reinterpret_cast<const float4*>(&KV[kk * ATT_V_STRIDE + tx * 4]);
            #pragma unroll
            for (int i = 0; i < 4; i++)
                #pragma unroll
                for (int j = 0; j < 4; j++)
                    oac[i][j] = fmaf(ap[i], vv[j], oac[i][j]);
        }
        __syncthreads();
    }

    #pragma unroll
    for (int i = 0; i < 4; i++) {
        int qr = q0 + ty * 4 + i;
        if (qr >= NTOK) continue;
        size_t o = ((size_t)b * NTOK + qr) * EMB + hh * HD + tx * 4;
        uint2 hp;
        hp.x = pack_h2(oac[i][0], oac[i][1]);
        hp.y = pack_h2(oac[i][2], oac[i][3]);
        *reinterpret_cast<uint2*>(&th[o]) = hp;
    }
}

// ---------------- fused residual add + LayerNorm (+ fp16 emit) --------------
__global__ __launch_bounds__(256)
void add_ln(const float* __restrict__ a, const float* __restrict__ b,
            const float* __restrict__ g, const float* __restrict__ be,
            float* __restrict__ out, __half* __restrict__ oh)
{
    const int r   = blockIdx.x;
    const int tid = threadIdx.x;
    float v[3];
    float s = 0.f, q = 0.f;
    #pragma unroll
    for (int t = 0; t < 3; t++) {
        int c = tid + t * 256;
        v[t] = a[(size_t)r * EMB + c] + b[(size_t)r * EMB + c];
        s += v[t];
        q += v[t] * v[t];
    }
    #pragma unroll
    for (int o = 16; o; o >>= 1) {
        s += __shfl_xor_sync(0xffffffffu, s, o);
        q += __shfl_xor_sync(0xffffffffu, q, o);
    }
    __shared__ float red[2][8];
    int w = tid >> 5, lane = tid & 31;
    if (lane == 0) { red[0][w] = s; red[1][w] = q; }
    __syncthreads();
    s = 0.f; q = 0.f;
    #pragma unroll
    for (int i = 0; i < 8; i++) { s += red[0][i]; q += red[1][i]; }
    float mean = s * (1.f / EMB);
    float var  = q * (1.f / EMB) - mean * mean;
    float rstd = rsqrtf(var + EPS);
    #pragma unroll
    for (int t = 0; t < 3; t++) {
        int c = tid + t * 256;
        float o = (v[t] - mean) * rstd * g[c] + be[c];
        size_t idx = (size_t)r * EMB + c;
        out[idx] = o;
        oh[idx]  = __float2half_rn(o);
    }
}

__global__ __launch_bounds__(256)
void cls_ln(const float* __restrict__ h, const float* __restrict__ g,
            const float* __restrict__ be, float* __restrict__ out)
{
    const int b   = blockIdx.x;
    const int tid = threadIdx.x;
    const float* row = h + (size_t)b * NTOK * EMB;
    float v[3];
    float s = 0.f, q = 0.f;
    #pragma unroll
    for (int t = 0; t < 3; t++) {
        int c = tid + t * 256;
        v[t] = row[c];
        s += v[t];
        q += v[t] * v[t];
    }
    #pragma unroll
    for (int o = 16; o; o >>= 1) {
        s += __shfl_xor_sync(0xffffffffu, s, o);
        q += __shfl_xor_sync(0xffffffffu, q, o);
    }
    __shared__ float red[2][8];
    int w = tid >> 5, lane = tid & 31;
    if (lane == 0) { red[0][w] = s; red[1][w] = q; }
    __syncthreads();
    s = 0.f; q = 0.f;
    #pragma unroll
    for (int i = 0; i < 8; i++) { s += red[0][i]; q += red[1][i]; }
    float mean = s * (1.f / EMB);
    float var  = q * (1.f / EMB) - mean * mean;
    float rstd = rsqrtf(var + EPS);
    #pragma unroll
    for (int t = 0; t < 3; t++) {
        int c = tid + t * 256;
        out[(size_t)b * EMB + c] = (v[t] - mean) * rstd * g[c] + be[c];
    }
}

// ---------------- classifier head -------------------------------------------
__global__ __launch_bounds__(256)
void head_gemm(const float* __restrict__ cls, const float* __restrict__ W,
               const float* __restrict__ bias, float* __restrict__ out)
{
    int idx = blockIdx.x * blockDim.x + threadIdx.x;
    if (idx >= BATCH * NCLS) return;
    int b = idx / NCLS;
    int n = idx % NCLS;
    float s = bias[n];
    const float* c = cls + (size_t)b * EMB;
    for (int k = 0; k < EMB; k++)
        s = fmaf(c[k], W[(size_t)k * NCLS + n], s);
    out[idx] = s;
}

// ---------------- driver -----------------------------------------------------
extern "C" void kernel_launch(void* const* d_in, const int* in_sizes, int n_in,
                              void* d_out, int out_size)
{
    const float* x        = (const float*)d_in[0];
    const float* conv_w   = (const float*)d_in[1];
    const float* conv_b   = (const float*)d_in[2];
    const float* cls_tok  = (const float*)d_in[3];
    const float* pos_emb  = (const float*)d_in[4];
    const float* Wq       = (const float*)d_in[5];
    const float* Wk       = (const float*)d_in[6];
    const float* Wv       = (const float*)d_in[7];
    const float* Wo       = (const float*)d_in[8];
    const float* bo       = (const float*)d_in[9];
    const float* ln1_g    = (const float*)d_in[10];
    const float* ln1_b    = (const float*)d_in[11];
    const float* W1       = (const float*)d_in[12];
    const float* b1       = (const float*)d_in[13];
    const float* W2       = (const float*)d_in[14];
    const float* b2       = (const float*)d_in[15];
    const float* ln2_g    = (const float*)d_in[16];
    const float* ln2_b    = (const float*)d_in[17];
    const float* head_g   = (const float*)d_in[18];
    const float* head_b   = (const float*)d_in[19];
    const float* head_W   = (const float*)d_in[20];
    const float* head_bias= (const float*)d_in[21];
    float* out = (float*)d_out;

    float *ph, *px, *pt, *pqkv, *pcls;
    __half *phh, *pxh, *pth, *pfh, *pimh, *pw, *pcw;
    cudaGetSymbolAddress((void**)&ph,   g_h);
    cudaGetSymbolAddress((void**)&px,   g_x);
    cudaGetSymbolAddress((void**)&pt,   g_t);
    cudaGetSymbolAddress((void**)&pqkv, g_qkv);
    cudaGetSymbolAddress((void**)&pcls, g_cls);
    cudaGetSymbolAddress((void**)&phh,  g_hh);
    cudaGetSymbolAddress((void**)&pxh,  g_xh);
    cudaGetSymbolAddress((void**)&pth,  g_th);
    cudaGetSymbolAddress((void**)&pfh,  g_fh);
    cudaGetSymbolAddress((void**)&pimh, g_imh);
    cudaGetSymbolAddress((void**)&pw,   g_w);
    cudaGetSymbolAddress((void**)&pcw,  g_cw);

    cudaFuncSetAttribute(gemm_hmma, cudaFuncAttributeMaxDynamicSharedMemorySize,
                         GEMM_SMEM);
    cudaFuncSetAttribute(attn_fused, cudaFuncAttributeMaxDynamicSharedMemorySize,
                         ATT_SMEM);

    // ---- weight prep: batched transpose to [N,K] fp16 ----
    {
        dim3 blk(32, 8);
        dim3 gEE(EMB/32, EMB/32, DEPTH);
        transpose_half_batch<<<gEE, blk>>>(Wq, pw + OFF_Q, EMB, EMB,
                                           (size_t)EMB*EMB, LSTRIDE);
        transpose_half_batch<<<gEE, blk>>>(Wk, pw + OFF_K, EMB, EMB,
                                           (size_t)EMB*EMB, LSTRIDE);
        transpose_half_batch<<<gEE, blk>>>(Wv, pw + OFF_V, EMB, EMB,
                                           (size_t)EMB*EMB, LSTRIDE);
        transpose_half_batch<<<gEE, blk>>>(Wo, pw + OFF_O, EMB, EMB,
                                           (size_t)EMB*EMB, LSTRIDE);
        dim3 g1(FF/32, EMB/32, DEPTH);
        transpose_half_batch<<<g1, blk>>>(W1, pw + OFF_W1, EMB, FF,
                                          (size_t)EMB*FF, LSTRIDE);
        dim3 g2(EMB/32, FF/32, DEPTH);
        transpose_half_batch<<<g2, blk>>>(W2, pw + OFF_W2, FF, EMB,
                                          (size_t)FF*EMB, LSTRIDE);
        tohalf_only<<<(EMB*EMB + 255)/256, 256>>>(conv_w, pcw, EMB*EMB);
    }

    // ---- patch embedding ----
    im2col_kernel<<<(PROWS*EMB + 255)/256, 256>>>(x, pimh);
    gemm_hmma<<<dim3(EMB/BN, PROWS/BM), 256, GEMM_SMEM>>>(
        pimh, pcw, conv_b, pt, nullptr, PROWS, EMB, EMB, 0);
    embed_kernel<<<(ROWS*EMB + 255)/256, 256>>>(pt, cls_tok, pos_emb, ph, phh);

    const int mtiles = (ROWS + BM - 1) / BM;   // 50
    const dim3 gQKV(QS/BN, mtiles);            // 18 x 50
    const dim3 gE(EMB/BN,  mtiles);            // 6 x 50
    const dim3 gF1(FF/BN,  mtiles);            // 24 x 50
    const dim3 gAT(4, BATCH*NHEAD);            // 64 q-rows per block

    for (int l = 0; l < DEPTH; l++) {
        size_t base = (size_t)l * LSTRIDE;
        const __half* qkvw = pw + base + OFF_Q;   // [2304, 768]
        const __half* ow   = pw + base + OFF_O;
        const __half* w1w  = pw + base + OFF_W1;
        const __half* w2w  = pw + base + OFF_W2;
        const float* bol= bo + (size_t)l*EMB;
        const float* g1 = ln1_g + (size_t)l*EMB;
        const float* be1= ln1_b + (size_t)l*EMB;
        const float* bb1= b1 + (size_t)l*FF;
        const float* bb2= b2 + (size_t)l*EMB;
        const float* g2 = ln2_g + (size_t)l*EMB;
        const float* be2= ln2_b + (size_t)l*EMB;

        gemm_hmma<<<gQKV, 256, GEMM_SMEM>>>(phh, qkvw, nullptr,
                                            pqkv, nullptr, ROWS, QS, EMB, 0);

        attn_fused<<<gAT, 256, ATT_SMEM>>>(pqkv, pth);

        gemm_hmma<<<gE, 256, GEMM_SMEM>>>(pth, ow, bol,
                                          pt, nullptr, ROWS, EMB, EMB, 0);
        add_ln<<<ROWS, 256>>>(pt, ph, g1, be1, px, pxh);

        gemm_hmma<<<gF1, 256, GEMM_SMEM>>>(pxh, w1w, bb1,
                                           nullptr, pfh, ROWS, FF, EMB, 1);
        gemm_hmma<<<gE, 256, GEMM_SMEM>>>(pfh, w2w, bb2,
                                          pt, nullptr, ROWS, EMB, FF, 0);
        add_ln<<<ROWS, 256>>>(pt, px, g2, be2, ph, phh);
    }

    cls_ln<<<BATCH, 256>>>(ph, head_g, head_b, pcls);
    head_gemm<<<(BATCH*NCLS + 255)/256, 256>>>(pcls, head_W, head_bias, out);
}

// round 9
// speedup vs baseline: 4.1109x; 1.0751x over previous
#include <cuda_runtime.h>
#include <cuda_fp16.h>
#include <cstdint>
#include <cstddef>

// ---------------- Problem constants ----------------
#define IMG   224
#define PATCH 16
#define EMB   768
#define DEPTH 12
#define NHEAD 12
#define HD    64
#define FF    3072
#define NCLS  1000
#define BATCH 32
#define NP    196
#define NTOK  197
#define ROWS  (BATCH * NTOK) // 6304
#define PROWS (BATCH * NP)   // 6272
#define EPS   1e-5f
#define QS    2304           // fused qkv row stride

// weight layout (per layer, element offsets). Q,K,V contiguous -> fused QKV.
#define OFF_Q   0
#define OFF_K   589824
#define OFF_V   1179648
#define OFF_O   1769472
#define OFF_W1  2359296
#define OFF_W2  4718592
#define LSTRIDE 7077888
#define WTOTAL  (LSTRIDE * DEPTH)

// ---------------- Scratch ----------------
__device__ float g_h  [ROWS * EMB];         // layer activation fp32 (trunk)
__device__ float g_x  [ROWS * EMB];         // post-LN1 fp32
__device__ float g_t  [2 * ROWS * EMB];     // split-K partial buffers (2x)
__device__ float g_qkv[ROWS * QS];          // fused qkv fp32
__device__ float g_cls[BATCH * EMB];
__device__ __half g_hh [ROWS * EMB];        // fp16 copies (GEMM A operands)
__device__ __half g_xh [ROWS * EMB];
__device__ __half g_th [ROWS * EMB];
__device__ __half g_fh [ROWS * FF];
__device__ __half g_imh[PROWS * EMB];
__device__ __half g_w  [WTOTAL];            // weights fp16, [N,K]
__device__ __half g_cw [EMB * EMB];

// ---------------- helpers ----------------
__device__ __forceinline__ uint32_t smem_u32(const void* p) {
    uint32_t a;
    asm("{ .reg .u64 t; cvta.to.shared.u64 t, %1; cvt.u32.u64 %0, t; }"
        : "=r"(a) : "l"(p));
    return a;
}
__device__ __forceinline__ void ldm_x4(uint32_t (&r)[4], uint32_t addr) {
    asm volatile("ldmatrix.sync.aligned.m8n8.x4.shared.b16 {%0,%1,%2,%3}, [%4];"
                 : "=r"(r[0]), "=r"(r[1]), "=r"(r[2]), "=r"(r[3]) : "r"(addr));
}
__device__ __forceinline__ void mma_f16(float (&d)[4], const uint32_t (&a)[4],
                                        const uint32_t (&b)[2]) {
    asm volatile("mma.sync.aligned.m16n8k16.row.col.f32.f16.f16.f32 "
                 "{%0,%1,%2,%3}, {%4,%5,%6,%7}, {%8,%9}, {%0,%1,%2,%3};"
                 : "+f"(d[0]), "+f"(d[1]), "+f"(d[2]), "+f"(d[3])
                 : "r"(a[0]), "r"(a[1]), "r"(a[2]), "r"(a[3]),
                   "r"(b[0]), "r"(b[1]));
}
__device__ __forceinline__ uint32_t pack_h2(float x, float y) {
    __half2 h = __floats2half2_rn(x, y);
    return *reinterpret_cast<uint32_t*>(&h);
}

// ---------------- weight prep: transpose [K,N] -> [N,K], fp16 ---------------
__global__ void transpose_half_batch(const float* __restrict__ W,
                                     __half* __restrict__ out,
                                     int K, int N,
                                     size_t w_lstride, size_t o_lstride)
{
    __shared__ float t[32][33];
    const int layer = blockIdx.z;
    W   += (size_t)layer * w_lstride;
    out += (size_t)layer * o_lstride;
    int nb = blockIdx.x * 32, kb = blockIdx.y * 32;
    int tx = threadIdx.x, ty = threadIdx.y;
    #pragma unroll
    for (int j = ty; j < 32; j += 8)
        t[j][tx] = W[(size_t)(kb + j) * N + nb + tx];
    __syncthreads();
    #pragma unroll
    for (int j = ty; j < 32; j += 8)
        out[(size_t)(nb + j) * K + kb + tx] = __float2half_rn(t[tx][j]);
}

__global__ void tohalf_only(const float* __restrict__ W,
                            __half* __restrict__ out, int n)
{
    int i = blockIdx.x * blockDim.x + threadIdx.x;
    if (i < n) out[i] = __float2half_rn(W[i]);
}

// ---------------- pipelined HMMA GEMM (single-pass fp16, fp32 accum) --------
// C[M,N] = A[M,:] @ B[N,:]^T over Kspan columns starting at blockIdx.z*Kspan.
// Row stride of A/B is ldK. Split-K partials land at Cf + z*M*N.
#define BM 128
#define BN 128
#define BK 64
#define ROWB 144                    // 64*2 + 16 pad bytes per smem row
#define ARR_B (128 * ROWB)          // 18432
#define STAGE_B (2 * ARR_B)         // 36864
#define GEMM_SMEM (2 * STAGE_B)     // 73728

__global__ __launch_bounds__(256, 2)
void gemm_hmma(const __half* __restrict__ A,
               const __half* __restrict__ B,
               const float* __restrict__ bias,
               float* __restrict__ Cf,
               __half* __restrict__ Ch,
               int M, int N, int Kspan, int ldK, int do_relu)
{
    extern __shared__ __align__(16) unsigned char dsm[];
    const uint32_t smb = smem_u32(dsm);
    const int tid  = threadIdx.x;
    const int lane = tid & 31;
    const int wid  = tid >> 5;
    const int wm   = wid & 1;
    const int wn   = wid >> 1;
    const int row0 = blockIdx.y * BM;
    const int col0 = blockIdx.x * BN;
    const int kz   = blockIdx.z;

    const __half* Ab = A + (size_t)kz * Kspan;
    const __half* Bb = B + (size_t)kz * Kspan;
    if (Cf) Cf += (size_t)kz * M * N;

    float acc[4][4][4] = {};

    auto load_stage = [&](int s, int kt) {
        #pragma unroll
        for (int l = 0; l < 8; l++) {
            int idx = tid + l * 256;     // 0..2047
            int arr = idx >> 10;         // 0 A, 1 B
            int w   = idx & 1023;
            int r   = w >> 3;            // 0..127
            int q   = w & 7;             // 16B unit
            int row = (arr ? col0 : row0) + r;
            const __half* src = (arr ? Bb : Ab) + (size_t)row * ldK + kt + q * 8;
            int bytes = (!arr && row >= M) ? 0 : 16;
            uint32_t dst = smb + (uint32_t)s * STAGE_B + (uint32_t)arr * ARR_B
                         + (uint32_t)r * ROWB + (uint32_t)q * 16u;
            asm volatile("cp.async.cg.shared.global [%0], [%1], 16, %2;"
                         :: "r"(dst), "l"(src), "r"(bytes) : "memory");
        }
        asm volatile("cp.async.commit_group;" ::: "memory");
    };

    auto compute_stage = [&](int s) {
        const uint32_t uA = smb + (uint32_t)s * STAGE_B;
        const uint32_t uB = uA + ARR_B;
        #pragma unroll
        for (int kk = 0; kk < 4; kk++) {
            const uint32_t kcb = (kk * 16 + ((lane >> 4) << 3)) * 2;
            uint32_t af[4][4];
            uint32_t bf[4][2];
            #pragma unroll
            for (int mi = 0; mi < 4; mi++) {
                uint32_t off = (uint32_t)(wm * 64 + mi * 16 + (lane & 15)) * ROWB + kcb;
                ldm_x4(af[mi], uA + off);
            }
            #pragma unroll
            for (int g = 0; g < 2; g++) {
                uint32_t off = (uint32_t)(wn * 32 + g * 16 + (lane & 15)) * ROWB + kcb;
                uint32_t tb[4];
                ldm_x4(tb, uB + off);
                bf[g*2+0][0] = tb[0]; bf[g*2+0][1] = tb[2];
                bf[g*2+1][0] = tb[1]; bf[g*2+1][1] = tb[3];
            }
            #pragma unroll
            for (int mi = 0; mi < 4; mi++)
                #pragma unroll
                for (int n = 0; n < 4; n++)
                    mma_f16(acc[mi][n], af[mi], bf[n]);
        }
    };

    const int nk = Kspan / BK;
    load_stage(0, 0);
    for (int i = 0; i < nk; i++) {
        const int cur = i & 1;
        if (i + 1 < nk) {
            load_stage(cur ^ 1, (i + 1) * BK);
            asm volatile("cp.async.wait_group 1;" ::: "memory");
        } else {
            asm volatile("cp.async.wait_group 0;" ::: "memory");
        }
        __syncthreads();
        compute_stage(cur);
        __syncthreads();
    }

    // ---- epilogue ----
    const bool hb = (bias != nullptr);
    #pragma unroll
    for (int mi = 0; mi < 4; mi++) {
        #pragma unroll
        for (int n = 0; n < 4; n++) {
            int gc = col0 + wn * 32 + n * 8 + (lane & 3) * 2;
            float bx = 0.f, by = 0.f;
            if (hb) { bx = bias[gc]; by = bias[gc + 1]; }
            #pragma unroll
            for (int h = 0; h < 2; h++) {
                int gr = row0 + wm * 64 + mi * 16 + (lane >> 2) + h * 8;
                if (gr >= M) continue;
                float ox = acc[mi][n][h * 2 + 0] + bx;
                float oy = acc[mi][n][h * 2 + 1] + by;
                if (do_relu) { ox = fmaxf(ox, 0.f); oy = fmaxf(oy, 0.f); }
                size_t o = (size_t)gr * N + gc;
                if (Cf)
                    *reinterpret_cast<float2*>(&Cf[o]) = make_float2(ox, oy);
                if (Ch)
                    *reinterpret_cast<uint32_t*>(&Ch[o]) = pack_h2(ox, oy);
            }
        }
    }
}

// ---------------- im2col (emits fp16) ---------------------------------------
__global__ void im2col_kernel(const float* __restrict__ x,
                              __half* __restrict__ ho)
{
    int idx = blockIdx.x * blockDim.x + threadIdx.x;
    if (idx >= PROWS * EMB) return;
    int row = idx / EMB;
    int k   = idx % EMB;
    int b   = row / NP;
    int p   = row % NP;
    int py  = p / 14, px = p % 14;
    int c   = k / 256;
    int r2  = k % 256;
    int ph  = r2 / PATCH, pw = r2 % PATCH;
    float v = x[(((size_t)b * 3 + c) * IMG + (py * PATCH + ph)) * IMG
                + (px * PATCH + pw)];
    ho[idx] = __float2half_rn(v);
}

__global__ void embed_kernel(const float* __restrict__ patch,
                             const float* __restrict__ cls_tok,
                             const float* __restrict__ pos,
                             float* __restrict__ h,
                             __half* __restrict__ hh)
{
    int idx = blockIdx.x * blockDim.x + threadIdx.x;
    if (idx >= ROWS * EMB) return;
    int row = idx / EMB;
    int e   = idx % EMB;
    int b   = row / NTOK;
    int n   = row % NTOK;
    float base = (n == 0) ? cls_tok[e]
                          : patch[((size_t)b * NP + (n - 1)) * EMB + e];
    float v = base + pos[n * EMB + e];
    h[idx]  = v;
    hh[idx] = __float2half_rn(v);
}

// ---------------- fused attention: 64 q-rows/block, 4x4 thread tiles --------
#define ATT_QS_STRIDE 68
#define ATT_KT_STRIDE 65
#define ATT_V_STRIDE  68
#define ATT_SC_STRIDE 260
#define ATT_Q_OFF  0
#define ATT_KV_OFF 4352
#define ATT_SC_OFF 8704
#define ATT_SMEM   ((8704 + 64 * ATT_SC_STRIDE) * 4)   // 101376 B

__global__ __launch_bounds__(256, 2)
void attn_fused(const float* __restrict__ qkv, __half* __restrict__ th)
{
    extern __shared__ __align__(16) float sm[];
    float* Qs = sm + ATT_Q_OFF;
    float* KV = sm + ATT_KV_OFF;
    float* SC = sm + ATT_SC_OFF;

    const int bh = blockIdx.y;
    const int b  = bh / NHEAD;
    const int hh = bh % NHEAD;
    const int q0 = blockIdx.x * 64;
    const float scale = 0.036084391824f;

    const int tid  = threadIdx.x;
    const int lane = tid & 31;
    const int wrp  = tid >> 5;
    const int tx   = tid & 15;
    const int ty   = tid >> 4;

    const float* Qb = qkv + (size_t)b * NTOK * QS + hh * HD;
    const float* Kb = Qb + 768;
    const float* Vb = Qb + 1536;

    #pragma unroll
    for (int l = 0; l < 4; l++) {
        int idx = tid + l * 256;
        int r   = idx >> 4;
        int c4  = (idx & 15) << 2;
        float4 vq = make_float4(0.f, 0.f, 0.f, 0.f);
        if (q0 + r < NTOK)
            vq = *reinterpret_cast<const float4*>(&Qb[(size_t)(q0 + r) * QS + c4]);
        float* qp = Qs + r * ATT_QS_STRIDE + c4;
        qp[0] = vq.x; qp[1] = vq.y; qp[2] = vq.z; qp[3] = vq.w;
    }
    __syncthreads();

    // ---- phase 1: scores ----
    for (int kt = 0; kt < 4; kt++) {
        #pragma unroll
        for (int l = 0; l < 4; l++) {
            int idx = tid + l * 256;
            int r   = idx >> 4;
            int c4  = (idx & 15) << 2;
            float4 vk = make_float4(0.f, 0.f, 0.f, 0.f);
            int kr = kt * 64 + r;
            if (kr < NTOK)
                vk = *reinterpret_cast<const float4*>(&Kb[(size_t)kr * QS + c4]);
            KV[(c4 + 0) * ATT_KT_STRIDE + r] = vk.x;
            KV[(c4 + 1) * ATT_KT_STRIDE + r] = vk.y;
            KV[(c4 + 2) * ATT_KT_STRIDE + r] = vk.z;
            KV[(c4 + 3) * ATT_KT_STRIDE + r] = vk.w;
        }
        __syncthreads();

        float acc[4][4] = {};
        #pragma unroll 8
        for (int kk = 0; kk < HD; kk++) {
            float aq[4], bk[4];
            #pragma unroll
            for (int i = 0; i < 4; i++)
                aq[i] = Qs[(ty * 4 + i) * ATT_QS_STRIDE + kk];
            #pragma unroll
            for (int j = 0; j < 4; j++)
                bk[j] = KV[kk * ATT_KT_STRIDE + tx * 4 + j];
            #pragma unroll
            for (int i = 0; i < 4; i++)
                #pragma unroll
                for (int j = 0; j < 4; j++)
                    acc[i][j] = fmaf(aq[i], bk[j], acc[i][j]);
        }
        #pragma unroll
        for (int i = 0; i < 4; i++)
            #pragma unroll
            for (int j = 0; j < 4; j++)
                SC[(ty * 4 + i) * ATT_SC_STRIDE + kt * 64 + tx * 4 + j]
                    = acc[i][j] * scale;
        __syncthreads();
    }

    // ---- phase 2: softmax ----
    #pragma unroll
    for (int rr = 0; rr < 8; rr++) {
        int row = wrp + rr * 8;
        float* p = SC + row * ATT_SC_STRIDE;
        float vals[7];
        float mx = -1e30f;
        #pragma unroll
        for (int i = 0; i < 7; i++) {
            int c = i * 32 + lane;
            vals[i] = (c < NTOK) ? p[c] : -1e30f;
            mx = fmaxf(mx, vals[i]);
        }
        #pragma unroll
        for (int o = 16; o; o >>= 1) mx = fmaxf(mx, __shfl_xor_sync(0xffffffffu, mx, o));
        float s = 0.f;
        #pragma unroll
        for (int i = 0; i < 7; i++) { vals[i] = expf(vals[i] - mx); s += vals[i]; }
        #pragma unroll
        for (int o = 16; o; o >>= 1) s += __shfl_xor_sync(0xffffffffu, s, o);
        float inv = 1.f / s;
        #pragma unroll
        for (int i = 0; i < 8; i++) {
            int c = i * 32 + lane;
            p[c] = (c < NTOK && i < 7) ? vals[i] * inv : 0.f;
        }
    }
    __syncthreads();

    // ---- phase 3: out = attn @ V ----
    float oac[4][4] = {};
    for (int kt = 0; kt < 4; kt++) {
        #pragma unroll
        for (int l = 0; l < 4; l++) {
            int idx = tid + l * 256;
            int r   = idx >> 4;
            int c4  = (idx & 15) << 2;
            float4 vv = make_float4(0.f, 0.f, 0.f, 0.f);
            int kr = kt * 64 + r;
            if (kr < NTOK)
                vv = *reinterpret_cast<const float4*>(&Vb[(size_t)kr * QS + c4]);
            *reinterpret_cast<float4*>(&KV[r * ATT_V_STRIDE + c4]) = vv;
        }
        __syncthreads();

        #pragma unroll 8
        for (int kk = 0; kk < 64; kk++) {
            float ap[4];
            #pragma unroll
            for (int i = 0; i < 4; i++)
                ap[i] = SC[(ty * 4 + i) * ATT_SC_STRIDE + kt * 64 + kk];
            float vv[4];
            *reinterpret_cast<float4*>(vv) =
                *reinterpret_cast<const float4*>(&KV[kk * ATT_V_STRIDE + tx * 4]);
            #pragma unroll
            for (int i = 0; i < 4; i++)
                #pragma unroll
                for (int j = 0; j < 4; j++)
                    oac[i][j] = fmaf(ap[i], vv[j], oac[i][j]);
        }
        __syncthreads();
    }

    #pragma unroll
    for (int i = 0; i < 4; i++) {
        int qr = q0 + ty * 4 + i;
        if (qr >= NTOK) continue;
        size_t o = ((size_t)b * NTOK + qr) * EMB + hh * HD + tx * 4;
        uint2 hp;
        hp.x = pack_h2(oac[i][0], oac[i][1]);
        hp.y = pack_h2(oac[i][2], oac[i][3]);
        *reinterpret_cast<uint2*>(&th[o]) = hp;
    }
}

// ------ fused split-K reduce + bias + residual add + LayerNorm + fp16 emit --
__global__ __launch_bounds__(256)
void add_ln(const float* __restrict__ a0, const float* __restrict__ a1,
            const float* __restrict__ abias,
            const float* __restrict__ b,
            const float* __restrict__ g, const float* __restrict__ be,
            float* __restrict__ out, __half* __restrict__ oh)
{
    const int r   = blockIdx.x;
    const int tid = threadIdx.x;
    float v[3];
    float s = 0.f, q = 0.f;
    #pragma unroll
    for (int t = 0; t < 3; t++) {
        int c = tid + t * 256;
        size_t idx = (size_t)r * EMB + c;
        v[t] = a0[idx] + a1[idx] + abias[c] + b[idx];
        s += v[t];
        q += v[t] * v[t];
    }
    #pragma unroll
    for (int o = 16; o; o >>= 1) {
        s += __shfl_xor_sync(0xffffffffu, s, o);
        q += __shfl_xor_sync(0xffffffffu, q, o);
    }
    __shared__ float red[2][8];
    int w = tid >> 5, lane = tid & 31;
    if (lane == 0) { red[0][w] = s; red[1][w] = q; }
    __syncthreads();
    s = 0.f; q = 0.f;
    #pragma unroll
    for (int i = 0; i < 8; i++) { s += red[0][i]; q += red[1][i]; }
    float mean = s * (1.f / EMB);
    float var  = q * (1.f / EMB) - mean * mean;
    float rstd = rsqrtf(var + EPS);
    #pragma unroll
    for (int t = 0; t < 3; t++) {
        int c = tid + t * 256;
        float o = (v[t] - mean) * rstd * g[c] + be[c];
        size_t idx = (size_t)r * EMB + c;
        out[idx] = o;
        oh[idx]  = __float2half_rn(o);
    }
}

__global__ __launch_bounds__(256)
void cls_ln(const float* __restrict__ h, const float* __restrict__ g,
            const float* __restrict__ be, float* __restrict__ out)
{
    const int b   = blockIdx.x;
    const int tid = threadIdx.x;
    const float* row = h + (size_t)b * NTOK * EMB;
    float v[3];
    float s = 0.f, q = 0.f;
    #pragma unroll
    for (int t = 0; t < 3; t++) {
        int c = tid + t * 256;
        v[t] = row[c];
        s += v[t];
        q += v[t] * v[t];
    }
    #pragma unroll
    for (int o = 16; o; o >>= 1) {
        s += __shfl_xor_sync(0xffffffffu, s, o);
        q += __shfl_xor_sync(0xffffffffu, q, o);
    }
    __shared__ float red[2][8];
    int w = tid >> 5, lane = tid & 31;
    if (lane == 0) { red[0][w] = s; red[1][w] = q; }
    __syncthreads();
    s = 0.f; q = 0.f;
    #pragma unroll
    for (int i = 0; i < 8; i++) { s += red[0][i]; q += red[1][i]; }
    float mean = s * (1.f / EMB);
    float var  = q * (1.f / EMB) - mean * mean;
    float rstd = rsqrtf(var + EPS);
    #pragma unroll
    for (int t = 0; t < 3; t++) {
        int c = tid + t * 256;
        out[(size_t)b * EMB + c] = (v[t] - mean) * rstd * g[c] + be[c];
    }
}

// ---------------- classifier head -------------------------------------------
__global__ __launch_bounds__(256)
void head_gemm(const float* __restrict__ cls, const float* __restrict__ W,
               const float* __restrict__ bias, float* __restrict__ out)
{
    int idx = blockIdx.x * blockDim.x + threadIdx.x;
    if (idx >= BATCH * NCLS) return;
    int b = idx / NCLS;
    int n = idx % NCLS;
    float s = bias[n];
    const float* c = cls + (size_t)b * EMB;
    for (int k = 0; k < EMB; k++)
        s = fmaf(c[k], W[(size_t)k * NCLS + n], s);
    out[idx] = s;
}

// ---------------- driver -----------------------------------------------------
extern "C" void kernel_launch(void* const* d_in, const int* in_sizes, int n_in,
                              void* d_out, int out_size)
{
    const float* x        = (const float*)d_in[0];
    const float* conv_w   = (const float*)d_in[1];
    const float* conv_b   = (const float*)d_in[2];
    const float* cls_tok  = (const float*)d_in[3];
    const float* pos_emb  = (const float*)d_in[4];
    const float* Wq       = (const float*)d_in[5];
    const float* Wk       = (const float*)d_in[6];
    const float* Wv       = (const float*)d_in[7];
    const float* Wo       = (const float*)d_in[8];
    const float* bo       = (const float*)d_in[9];
    const float* ln1_g    = (const float*)d_in[10];
    const float* ln1_b    = (const float*)d_in[11];
    const float* W1       = (const float*)d_in[12];
    const float* b1       = (const float*)d_in[13];
    const float* W2       = (const float*)d_in[14];
    const float* b2       = (const float*)d_in[15];
    const float* ln2_g    = (const float*)d_in[16];
    const float* ln2_b    = (const float*)d_in[17];
    const float* head_g   = (const float*)d_in[18];
    const float* head_b   = (const float*)d_in[19];
    const float* head_W   = (const float*)d_in[20];
    const float* head_bias= (const float*)d_in[21];
    float* out = (float*)d_out;

    float *ph, *px, *pt, *pqkv, *pcls;
    __half *phh, *pxh, *pth, *pfh, *pimh, *pw, *pcw;
    cudaGetSymbolAddress((void**)&ph,   g_h);
    cudaGetSymbolAddress((void**)&px,   g_x);
    cudaGetSymbolAddress((void**)&pt,   g_t);
    cudaGetSymbolAddress((void**)&pqkv, g_qkv);
    cudaGetSymbolAddress((void**)&pcls, g_cls);
    cudaGetSymbolAddress((void**)&phh,  g_hh);
    cudaGetSymbolAddress((void**)&pxh,  g_xh);
    cudaGetSymbolAddress((void**)&pth,  g_th);
    cudaGetSymbolAddress((void**)&pfh,  g_fh);
    cudaGetSymbolAddress((void**)&pimh, g_imh);
    cudaGetSymbolAddress((void**)&pw,   g_w);
    cudaGetSymbolAddress((void**)&pcw,  g_cw);
    float* pt2 = pt + (size_t)ROWS * EMB;

    cudaFuncSetAttribute(gemm_hmma, cudaFuncAttributeMaxDynamicSharedMemorySize,
                         GEMM_SMEM);
    cudaFuncSetAttribute(attn_fused, cudaFuncAttributeMaxDynamicSharedMemorySize,
                         ATT_SMEM);

    // ---- weight prep: batched transpose to [N,K] fp16 ----
    {
        dim3 blk(32, 8);
        dim3 gEE(EMB/32, EMB/32, DEPTH);
        transpose_half_batch<<<gEE, blk>>>(Wq, pw + OFF_Q, EMB, EMB,
                                           (size_t)EMB*EMB, LSTRIDE);
        transpose_half_batch<<<gEE, blk>>>(Wk, pw + OFF_K, EMB, EMB,
                                           (size_t)EMB*EMB, LSTRIDE);
        transpose_half_batch<<<gEE, blk>>>(Wv, pw + OFF_V, EMB, EMB,
                                           (size_t)EMB*EMB, LSTRIDE);
        transpose_half_batch<<<gEE, blk>>>(Wo, pw + OFF_O, EMB, EMB,
                                           (size_t)EMB*EMB, LSTRIDE);
        dim3 g1(FF/32, EMB/32, DEPTH);
        transpose_half_batch<<<g1, blk>>>(W1, pw + OFF_W1, EMB, FF,
                                          (size_t)EMB*FF, LSTRIDE);
        dim3 g2(EMB/32, FF/32, DEPTH);
        transpose_half_batch<<<g2, blk>>>(W2, pw + OFF_W2, FF, EMB,
                                          (size_t)FF*EMB, LSTRIDE);
        tohalf_only<<<(EMB*EMB + 255)/256, 256>>>(conv_w, pcw, EMB*EMB);
    }

    // ---- patch embedding ----
    im2col_kernel<<<(PROWS*EMB + 255)/256, 256>>>(x, pimh);
    gemm_hmma<<<dim3(EMB/BN, PROWS/BM, 1), 256, GEMM_SMEM>>>(
        pimh, pcw, conv_b, pt, nullptr, PROWS, EMB, EMB, EMB, 0);
    embed_kernel<<<(ROWS*EMB + 255)/256, 256>>>(pt, cls_tok, pos_emb, ph, phh);

    const int mtiles = (ROWS + BM - 1) / BM;     // 50
    const dim3 gQKV(QS/BN, mtiles, 1);           // 18 x 50
    const dim3 gEs(EMB/BN, mtiles, 2);           // 6 x 50 x 2 (split-K)
    const dim3 gF1(FF/BN,  mtiles, 1);           // 24 x 50
    const dim3 gAT(4, BATCH*NHEAD);

    for (int l = 0; l < DEPTH; l++) {
        size_t base = (size_t)l * LSTRIDE;
        const __half* qkvw = pw + base + OFF_Q;   // [2304, 768]
        const __half* ow   = pw + base + OFF_O;
        const __half* w1w  = pw + base + OFF_W1;
        const __half* w2w  = pw + base + OFF_W2;
        const float* bol= bo + (size_t)l*EMB;
        const float* g1 = ln1_g + (size_t)l*EMB;
        const float* be1= ln1_b + (size_t)l*EMB;
        const float* bb1= b1 + (size_t)l*FF;
        const float* bb2= b2 + (size_t)l*EMB;
        const float* g2 = ln2_g + (size_t)l*EMB;
        const float* be2= ln2_b + (size_t)l*EMB;

        gemm_hmma<<<gQKV, 256, GEMM_SMEM>>>(phh, qkvw, nullptr,
                                            pqkv, nullptr, ROWS, QS, EMB, EMB, 0);

        attn_fused<<<gAT, 256, ATT_SMEM>>>(pqkv, pth);

        // O-proj split-K2: partials in pt/pt2; bias folded into add_ln
        gemm_hmma<<<gEs, 256, GEMM_SMEM>>>(pth, ow, nullptr,
                                           pt, nullptr, ROWS, EMB, 384, EMB, 0);
        add_ln<<<ROWS, 256>>>(pt, pt2, bol, ph, g1, be1, px, pxh);

        gemm_hmma<<<gF1, 256, GEMM_SMEM>>>(pxh, w1w, bb1,
                                           nullptr, pfh, ROWS, FF, EMB, EMB, 1);
        // FF2 split-K2
        gemm_hmma<<<gEs, 256, GEMM_SMEM>>>(pfh, w2w, nullptr,
                                           pt, nullptr, ROWS, EMB, 1536, FF, 0);
        add_ln<<<ROWS, 256>>>(pt, pt2, bb2, px, g2, be2, ph, phh);
    }

    cls_ln<<<BATCH, 256>>>(ph, head_g, head_b, pcls);
    head_gemm<<<(BATCH*NCLS + 255)/256, 256>>>(pcls, head_W, head_bias, out);
}